// round 1
// baseline (speedup 1.0000x reference)
#include <cuda_runtime.h>
#include <math.h>

#define D 768
#define NN 64
#define BS 512
#define ROWSTRIDE 832   // D + NN
#define NEG_SLOPE 0.2f

// Scratch (allocation-free rule: __device__ globals). 96 MB each.
__device__ float g_hp[BS * NN * D];   // GEMM output / also reused as concat-vec buffer (512x1536)
__device__ float g_h[BS * NN * D];    // attention output (next-layer input)

// ---------------------------------------------------------------------------
// GEMM: C(g_hp) = A @ W, A is (32768 x 768) with row stride lda, W is 768x768.
// layer==0: A = batch (lda=832, first 768 cols). layer!=0: A = g_h (lda=768).
// 128x128 block tile, 16 k-tile, 8x8 per-thread microtile, 256 threads.
// ---------------------------------------------------------------------------
__global__ __launch_bounds__(256) void gemm_kernel(const float* __restrict__ batch,
                                                   int layer,
                                                   const float* __restrict__ W) {
    __shared__ float As[16][128];   // transposed A tile: As[k][m]
    __shared__ float Bs[16][128];   // Bs[k][n]

    const float* A;
    int lda;
    if (layer == 0) { A = batch; lda = ROWSTRIDE; }
    else            { A = g_h;   lda = D; }

    const int tid = threadIdx.x;
    const int bm = blockIdx.y * 128;
    const int bn = blockIdx.x * 128;
    const int ty = tid >> 4;   // 0..15
    const int tx = tid & 15;   // 0..15

    float acc[8][8];
#pragma unroll
    for (int i = 0; i < 8; i++)
#pragma unroll
        for (int j = 0; j < 8; j++) acc[i][j] = 0.f;

    for (int k0 = 0; k0 < D; k0 += 16) {
        // Load A tile: 128 rows x 16 k = 512 float4, 2 per thread.
#pragma unroll
        for (int i = 0; i < 2; i++) {
            int idx = tid * 2 + i;
            int r = idx >> 2;
            int kq = (idx & 3) << 2;
            const float4 v = *(const float4*)(A + (size_t)(bm + r) * lda + k0 + kq);
            As[kq + 0][r] = v.x;
            As[kq + 1][r] = v.y;
            As[kq + 2][r] = v.z;
            As[kq + 3][r] = v.w;
        }
        // Load B tile: 16 rows x 128 cols = 512 float4, 2 per thread.
#pragma unroll
        for (int i = 0; i < 2; i++) {
            int idx = tid * 2 + i;
            int r = idx >> 5;
            int c4 = (idx & 31) << 2;
            *(float4*)(&Bs[r][c4]) = *(const float4*)(W + (size_t)(k0 + r) * D + bn + c4);
        }
        __syncthreads();

#pragma unroll
        for (int k = 0; k < 16; k++) {
            float ra[8], rb[8];
#pragma unroll
            for (int i = 0; i < 8; i++) ra[i] = As[k][ty * 8 + i];
#pragma unroll
            for (int j = 0; j < 8; j++) rb[j] = Bs[k][tx * 8 + j];
#pragma unroll
            for (int i = 0; i < 8; i++)
#pragma unroll
                for (int j = 0; j < 8; j++)
                    acc[i][j] = fmaf(ra[i], rb[j], acc[i][j]);
        }
        __syncthreads();
    }

#pragma unroll
    for (int i = 0; i < 8; i++) {
        float* crow = g_hp + (size_t)(bm + ty * 8 + i) * D + bn + tx * 8;
        *(float4*)(crow + 0) = make_float4(acc[i][0], acc[i][1], acc[i][2], acc[i][3]);
        *(float4*)(crow + 4) = make_float4(acc[i][4], acc[i][5], acc[i][6], acc[i][7]);
    }
}

// ---------------------------------------------------------------------------
// Attention: per graph (1 CTA, 256 thr):
//   src[i] = sum_o tanh(hp[i][o]) * a_src[o]   (dst analogous)
//   e[i][j] = leakyrelu(src[i]+dst[j]); mask by (adj || eye); row softmax
//   h_out = attn @ hp + bias
// reads g_hp, writes g_h.
// ---------------------------------------------------------------------------
__global__ __launch_bounds__(256) void attn_kernel(const float* __restrict__ batch,
                                                   const float* __restrict__ a_src,
                                                   const float* __restrict__ a_dst,
                                                   const float* __restrict__ bias) {
    __shared__ float s_attn[64][65];  // padded: avoid bank conflicts on row-varied reads
    __shared__ float s_hs[64][68];    // hp chunk (64 rows x 64 cols), padded for STS.128
    __shared__ float s_src[64];
    __shared__ float s_dst[64];

    const int b = blockIdx.x;
    const int tid = threadIdx.x;
    const int warp = tid >> 5;
    const int lane = tid & 31;
    const float* HP = g_hp + (size_t)b * NN * D;

    // ---- 1. src/dst row dots (warp per row, 8 rows per warp) ----
    for (int i = warp; i < NN; i += 8) {
        float s = 0.f, dd = 0.f;
        const float* hrow = HP + (size_t)i * D;
        for (int o = lane; o < D; o += 32) {
            float t = tanhf(hrow[o]);
            s  = fmaf(t, a_src[o], s);
            dd = fmaf(t, a_dst[o], dd);
        }
#pragma unroll
        for (int off = 16; off; off >>= 1) {
            s  += __shfl_xor_sync(0xffffffffu, s, off);
            dd += __shfl_xor_sync(0xffffffffu, dd, off);
        }
        if (lane == 0) { s_src[i] = s; s_dst[i] = dd; }
    }
    __syncthreads();

    // ---- 2. attention scores + softmax (warp per row) ----
    for (int i = warp; i < NN; i += 8) {
        const float* arow = batch + ((size_t)b * NN + i) * ROWSTRIDE + D;
        float e0, e1;
        {
            int j = lane;
            float v = s_src[i] + s_dst[j];
            v = (v >= 0.f) ? v : NEG_SLOPE * v;
            bool allowed = (arow[j] != 0.f) || (i == j);
            e0 = allowed ? v : -INFINITY;
        }
        {
            int j = lane + 32;
            float v = s_src[i] + s_dst[j];
            v = (v >= 0.f) ? v : NEG_SLOPE * v;
            bool allowed = (arow[j] != 0.f) || (i == j);
            e1 = allowed ? v : -INFINITY;
        }
        float mx = fmaxf(e0, e1);
#pragma unroll
        for (int off = 16; off; off >>= 1)
            mx = fmaxf(mx, __shfl_xor_sync(0xffffffffu, mx, off));
        float x0 = (e0 == -INFINITY) ? 0.f : __expf(e0 - mx);
        float x1 = (e1 == -INFINITY) ? 0.f : __expf(e1 - mx);
        float sum = x0 + x1;
#pragma unroll
        for (int off = 16; off; off >>= 1)
            sum += __shfl_xor_sync(0xffffffffu, sum, off);
        float inv = 1.f / sum;
        s_attn[i][lane]      = x0 * inv;
        s_attn[i][lane + 32] = x1 * inv;
    }
    __syncthreads();

    // ---- 3. out = attn @ hp + bias, 64-col chunks ----
    const int c0 = (tid & 7) * 8;   // 8 col groups of 8
    const int i0 = tid >> 3;        // 0..31 (rows i0, i0+32)
    float* HOUT = g_h + (size_t)b * NN * D;

    for (int dc = 0; dc < D; dc += 64) {
        for (int t = tid; t < 64 * 16; t += 256) {
            int r = t >> 4;
            int c4 = (t & 15) << 2;
            *(float4*)(&s_hs[r][c4]) = *(const float4*)(HP + (size_t)r * D + dc + c4);
        }
        __syncthreads();
#pragma unroll
        for (int rr = 0; rr < 2; rr++) {
            int i = i0 + 32 * rr;
            float acc[8];
#pragma unroll
            for (int u = 0; u < 8; u++) acc[u] = 0.f;
            for (int j = 0; j < 64; j++) {
                float a = s_attn[i][j];
#pragma unroll
                for (int u = 0; u < 8; u++)
                    acc[u] = fmaf(a, s_hs[j][c0 + u], acc[u]);
            }
            float* orow = HOUT + (size_t)i * D + dc + c0;
#pragma unroll
            for (int u = 0; u < 8; u++) orow[u] = acc[u] + bias[dc + c0 + u];
        }
        __syncthreads();
    }
}

// ---------------------------------------------------------------------------
// final1: per graph build vec = [center (batch row 0 features), l2norm(h2[0])]
// into g_hp (reused as 512 x 1536 buffer).
// ---------------------------------------------------------------------------
__global__ __launch_bounds__(256) void final1_kernel(const float* __restrict__ batch) {
    const int b = blockIdx.x;
    const int tid = threadIdx.x;
    const int warp = tid >> 5, lane = tid & 31;
    __shared__ float red[8];

    const float* h0 = g_h + (size_t)b * NN * D;   // row 0
    float ss = 0.f;
    for (int o = tid; o < D; o += 256) { float v = h0[o]; ss = fmaf(v, v, ss); }
#pragma unroll
    for (int off = 16; off; off >>= 1) ss += __shfl_xor_sync(0xffffffffu, ss, off);
    if (lane == 0) red[warp] = ss;
    __syncthreads();
    float tot = red[0];
#pragma unroll
    for (int w = 1; w < 8; w++) tot += red[w];
    float inv = 1.f / fmaxf(sqrtf(tot), 1e-12f);

    float* vec = g_hp + (size_t)b * 1536;
    const float* crow = batch + (size_t)b * NN * ROWSTRIDE;  // node 0 features
    for (int o = tid; o < D; o += 256) {
        vec[o]     = crow[o];
        vec[D + o] = h0[o] * inv;
    }
}

// ---------------------------------------------------------------------------
// final2: 4 graphs per CTA, out[b][o] = l2norm( vec[b] . mlp_w[o] + mlp_b[o] )
// Warp-per-output-row; the mlp_w row read is amortized over 4 graphs.
// ---------------------------------------------------------------------------
__global__ __launch_bounds__(256) void final2_kernel(const float* __restrict__ mlp_w,
                                                     const float* __restrict__ mlp_b,
                                                     float* __restrict__ out) {
    __shared__ float sv[4][1536];   // 24 KB
    __shared__ float sout[4][768];  // 12 KB
    const int b0 = blockIdx.x * 4;
    const int tid = threadIdx.x;
    const int warp = tid >> 5, lane = tid & 31;

    for (int t = tid; t < 4 * 384; t += 256) {
        int g = t / 384;
        int k4 = (t % 384) << 2;
        *(float4*)(&sv[g][k4]) = *(const float4*)(g_hp + (size_t)(b0 + g) * 1536 + k4);
    }
    __syncthreads();

    for (int o = warp; o < 768; o += 8) {
        const float* wr = mlp_w + (size_t)o * 1536;
        float a0 = 0.f, a1 = 0.f, a2 = 0.f, a3 = 0.f;
        for (int k4 = lane * 4; k4 < 1536; k4 += 128) {
            float4 wv = *(const float4*)(wr + k4);
            float4 x;
            x = *(const float4*)(&sv[0][k4]); a0 += wv.x*x.x + wv.y*x.y + wv.z*x.z + wv.w*x.w;
            x = *(const float4*)(&sv[1][k4]); a1 += wv.x*x.x + wv.y*x.y + wv.z*x.z + wv.w*x.w;
            x = *(const float4*)(&sv[2][k4]); a2 += wv.x*x.x + wv.y*x.y + wv.z*x.z + wv.w*x.w;
            x = *(const float4*)(&sv[3][k4]); a3 += wv.x*x.x + wv.y*x.y + wv.z*x.z + wv.w*x.w;
        }
#pragma unroll
        for (int off = 16; off; off >>= 1) {
            a0 += __shfl_xor_sync(0xffffffffu, a0, off);
            a1 += __shfl_xor_sync(0xffffffffu, a1, off);
            a2 += __shfl_xor_sync(0xffffffffu, a2, off);
            a3 += __shfl_xor_sync(0xffffffffu, a3, off);
        }
        if (lane == 0) {
            float bo = mlp_b[o];
            sout[0][o] = a0 + bo;
            sout[1][o] = a1 + bo;
            sout[2][o] = a2 + bo;
            sout[3][o] = a3 + bo;
        }
    }
    __syncthreads();

    if (warp < 4) {
        float ss = 0.f;
        for (int o = lane; o < 768; o += 32) { float v = sout[warp][o]; ss = fmaf(v, v, ss); }
#pragma unroll
        for (int off = 16; off; off >>= 1) ss += __shfl_xor_sync(0xffffffffu, ss, off);
        float inv = 1.f / fmaxf(sqrtf(ss), 1e-12f);
        for (int o = lane; o < 768; o += 32)
            out[(size_t)(b0 + warp) * 768 + o] = sout[warp][o] * inv;
    }
}

// ---------------------------------------------------------------------------
extern "C" void kernel_launch(void* const* d_in, const int* in_sizes, int n_in,
                              void* d_out, int out_size) {
    const float* batch = (const float*)d_in[0];
    const float* w     = (const float*)d_in[1];
    const float* a_src = (const float*)d_in[2];
    const float* a_dst = (const float*)d_in[3];
    const float* gbias = (const float*)d_in[4];
    const float* mlp_w = (const float*)d_in[5];
    const float* mlp_b = (const float*)d_in[6];
    float* out = (float*)d_out;

    dim3 gg(6, 256);  // 768/128 cols x 32768/128 rows
    // Layer 1
    gemm_kernel<<<gg, 256>>>(batch, 0, w);
    attn_kernel<<<512, 256>>>(batch, a_src, a_dst, gbias);
    // Layer 2
    gemm_kernel<<<gg, 256>>>(batch, 1, w);
    attn_kernel<<<512, 256>>>(batch, a_src, a_dst, gbias);
    // Head
    final1_kernel<<<512, 256>>>(batch);
    final2_kernel<<<128, 256>>>(mlp_w, mlp_b, out);
}

// round 2
// speedup vs baseline: 2.6197x; 2.6197x over previous
#include <cuda_runtime.h>
#include <math.h>
#include <stdint.h>

#define D 768
#define NN 64
#define BS 512
#define ROWSTRIDE 832   // D + NN
#define NEG_SLOPE 0.2f

// Scratch (allocation-free rule: __device__ globals). 96 MB each.
__device__ float g_hp[BS * NN * D];   // GEMM output / reused as concat-vec buffer (512x1536)
__device__ float g_h[BS * NN * D];    // attention output (next-layer input)

__device__ __forceinline__ float tf32r(float x) {
    uint32_t u;
    asm("cvt.rna.tf32.f32 %0, %1;" : "=r"(u) : "f"(x));
    return __uint_as_float(u);
}

// ---------------------------------------------------------------------------
// TF32 tensor-core GEMM: g_hp = A @ W
// A is (32768 x 768): layer 0 -> batch rows (lda=832), layer 1 -> g_h (lda=768)
// CTA tile 128x128, BK=32, 256 threads = 8 warps in 2(m) x 4(n), warp tile 64x32.
// mma.sync.aligned.m16n8k8.row.col.f32.tf32.tf32.f32
// ---------------------------------------------------------------------------
__global__ __launch_bounds__(256) void gemm_tf32_kernel(const float* __restrict__ batch,
                                                        int layer,
                                                        const float* __restrict__ W) {
    __shared__ float As[128][36];   // [m][k], pad 36 -> conflict-free frag reads
    __shared__ float Bs[32][136];   // [k][n], pad 136 -> conflict-free frag reads

    const float* A;
    int lda;
    if (layer == 0) { A = batch; lda = ROWSTRIDE; }
    else            { A = g_h;   lda = D; }

    const int tid  = threadIdx.x;
    const int bm   = blockIdx.y * 128;
    const int bn   = blockIdx.x * 128;
    const int wid  = tid >> 5;
    const int lane = tid & 31;
    const int wm   = (wid >> 2) * 64;   // 0 or 64
    const int wn   = (wid & 3) * 32;    // 0,32,64,96
    const int qr   = lane >> 2;         // 0..7
    const int qc   = lane & 3;          // 0..3

    float acc[4][4][4];
#pragma unroll
    for (int mi = 0; mi < 4; mi++)
#pragma unroll
        for (int ni = 0; ni < 4; ni++)
#pragma unroll
            for (int u = 0; u < 4; u++) acc[mi][ni][u] = 0.f;

    float4 pa[4], pb[4];

    // prefetch tile 0
#pragma unroll
    for (int i = 0; i < 4; i++) {
        int idx = i * 256 + tid;
        int r = idx >> 3, q = idx & 7;           // A: row r, k-chunk q*4
        pa[i] = *(const float4*)(A + (size_t)(bm + r) * lda + q * 4);
        int rb = idx >> 5, c4 = (idx & 31) << 2; // B: k-row rb, n-chunk c4
        pb[i] = *(const float4*)(W + (size_t)rb * D + bn + c4);
    }

#pragma unroll 1
    for (int t = 0; t < 24; t++) {
        // stage prefetched tile into smem (with tf32 round-nearest)
#pragma unroll
        for (int i = 0; i < 4; i++) {
            int idx = i * 256 + tid;
            int r = idx >> 3, q = idx & 7;
            float4 v = pa[i];
            v.x = tf32r(v.x); v.y = tf32r(v.y); v.z = tf32r(v.z); v.w = tf32r(v.w);
            *(float4*)(&As[r][q * 4]) = v;
            int rb = idx >> 5, c4 = (idx & 31) << 2;
            float4 w4 = pb[i];
            w4.x = tf32r(w4.x); w4.y = tf32r(w4.y); w4.z = tf32r(w4.z); w4.w = tf32r(w4.w);
            *(float4*)(&Bs[rb][c4]) = w4;
        }
        __syncthreads();

        // prefetch next tile
        if (t + 1 < 24) {
            int k0 = (t + 1) * 32;
#pragma unroll
            for (int i = 0; i < 4; i++) {
                int idx = i * 256 + tid;
                int r = idx >> 3, q = idx & 7;
                pa[i] = *(const float4*)(A + (size_t)(bm + r) * lda + k0 + q * 4);
                int rb = idx >> 5, c4 = (idx & 31) << 2;
                pb[i] = *(const float4*)(W + (size_t)(k0 + rb) * D + bn + c4);
            }
        }

        // compute 4 k8-steps
#pragma unroll
        for (int kk = 0; kk < 32; kk += 8) {
            float a[4][4];
#pragma unroll
            for (int mi = 0; mi < 4; mi++) {
                int r = wm + mi * 16 + qr;
                a[mi][0] = As[r][kk + qc];
                a[mi][1] = As[r + 8][kk + qc];
                a[mi][2] = As[r][kk + qc + 4];
                a[mi][3] = As[r + 8][kk + qc + 4];
            }
            float b[4][2];
#pragma unroll
            for (int ni = 0; ni < 4; ni++) {
                int c = wn + ni * 8 + qr;
                b[ni][0] = Bs[kk + qc][c];
                b[ni][1] = Bs[kk + qc + 4][c];
            }
#pragma unroll
            for (int mi = 0; mi < 4; mi++)
#pragma unroll
                for (int ni = 0; ni < 4; ni++) {
                    asm volatile(
                        "mma.sync.aligned.m16n8k8.row.col.f32.tf32.tf32.f32 "
                        "{%0,%1,%2,%3}, {%4,%5,%6,%7}, {%8,%9}, {%0,%1,%2,%3};"
                        : "+f"(acc[mi][ni][0]), "+f"(acc[mi][ni][1]),
                          "+f"(acc[mi][ni][2]), "+f"(acc[mi][ni][3])
                        : "r"(__float_as_uint(a[mi][0])), "r"(__float_as_uint(a[mi][1])),
                          "r"(__float_as_uint(a[mi][2])), "r"(__float_as_uint(a[mi][3])),
                          "r"(__float_as_uint(b[ni][0])), "r"(__float_as_uint(b[ni][1])));
                }
        }
        __syncthreads();
    }

    // epilogue
#pragma unroll
    for (int mi = 0; mi < 4; mi++) {
#pragma unroll
        for (int ni = 0; ni < 4; ni++) {
            int row = bm + wm + mi * 16 + qr;
            int col = bn + wn + ni * 8 + qc * 2;
            *(float2*)(&g_hp[(size_t)row * D + col]) =
                make_float2(acc[mi][ni][0], acc[mi][ni][1]);
            *(float2*)(&g_hp[(size_t)(row + 8) * D + col]) =
                make_float2(acc[mi][ni][2], acc[mi][ni][3]);
        }
    }
}

// ---------------------------------------------------------------------------
// Attention: per graph (1 CTA, 256 thr). Reads g_hp, writes g_h.
// ---------------------------------------------------------------------------
__global__ __launch_bounds__(256) void attn_kernel(const float* __restrict__ batch,
                                                   const float* __restrict__ a_src,
                                                   const float* __restrict__ a_dst,
                                                   const float* __restrict__ bias) {
    __shared__ float s_attn[64][65];
    __shared__ float s_hs[64][68];
    __shared__ float s_src[64];
    __shared__ float s_dst[64];

    const int b = blockIdx.x;
    const int tid = threadIdx.x;
    const int warp = tid >> 5;
    const int lane = tid & 31;
    const float* HP = g_hp + (size_t)b * NN * D;

    // ---- 1. src/dst row dots (warp per row), float4 vectorized ----
    for (int i = warp; i < NN; i += 8) {
        float s = 0.f, dd = 0.f;
        const float* hrow = HP + (size_t)i * D;
#pragma unroll
        for (int o4 = lane * 4; o4 < D; o4 += 128) {
            float4 h  = *(const float4*)(hrow + o4);
            float4 as = *(const float4*)(a_src + o4);
            float4 ad = *(const float4*)(a_dst + o4);
            float t0 = tanhf(h.x), t1 = tanhf(h.y), t2 = tanhf(h.z), t3 = tanhf(h.w);
            s  = fmaf(t0, as.x, fmaf(t1, as.y, fmaf(t2, as.z, fmaf(t3, as.w, s))));
            dd = fmaf(t0, ad.x, fmaf(t1, ad.y, fmaf(t2, ad.z, fmaf(t3, ad.w, dd))));
        }
#pragma unroll
        for (int off = 16; off; off >>= 1) {
            s  += __shfl_xor_sync(0xffffffffu, s, off);
            dd += __shfl_xor_sync(0xffffffffu, dd, off);
        }
        if (lane == 0) { s_src[i] = s; s_dst[i] = dd; }
    }
    __syncthreads();

    // ---- 2. attention scores + softmax (warp per row) ----
    for (int i = warp; i < NN; i += 8) {
        const float* arow = batch + ((size_t)b * NN + i) * ROWSTRIDE + D;
        float e0, e1;
        {
            int j = lane;
            float v = s_src[i] + s_dst[j];
            v = (v >= 0.f) ? v : NEG_SLOPE * v;
            bool allowed = (arow[j] != 0.f) || (i == j);
            e0 = allowed ? v : -INFINITY;
        }
        {
            int j = lane + 32;
            float v = s_src[i] + s_dst[j];
            v = (v >= 0.f) ? v : NEG_SLOPE * v;
            bool allowed = (arow[j] != 0.f) || (i == j);
            e1 = allowed ? v : -INFINITY;
        }
        float mx = fmaxf(e0, e1);
#pragma unroll
        for (int off = 16; off; off >>= 1)
            mx = fmaxf(mx, __shfl_xor_sync(0xffffffffu, mx, off));
        float x0 = (e0 == -INFINITY) ? 0.f : __expf(e0 - mx);
        float x1 = (e1 == -INFINITY) ? 0.f : __expf(e1 - mx);
        float sum = x0 + x1;
#pragma unroll
        for (int off = 16; off; off >>= 1)
            sum += __shfl_xor_sync(0xffffffffu, sum, off);
        float inv = 1.f / sum;
        s_attn[i][lane]      = x0 * inv;
        s_attn[i][lane + 32] = x1 * inv;
    }
    __syncthreads();

    // ---- 3. out = attn @ hp + bias ----
    // thread -> 4 cols ((tid&15)*4) x 4 rows (tid>>4, +16, +32, +48)
    const int c0 = (tid & 15) * 4;
    const int i0 = tid >> 4;
    float* HOUT = g_h + (size_t)b * NN * D;

    for (int dc = 0; dc < D; dc += 64) {
        for (int t = tid; t < 64 * 16; t += 256) {
            int r = t >> 4;
            int c4 = (t & 15) << 2;
            *(float4*)(&s_hs[r][c4]) = *(const float4*)(HP + (size_t)r * D + dc + c4);
        }
        __syncthreads();

        float acc[4][4];
#pragma unroll
        for (int r = 0; r < 4; r++)
#pragma unroll
            for (int u = 0; u < 4; u++) acc[r][u] = 0.f;

#pragma unroll 4
        for (int j = 0; j < 64; j++) {
            float4 hv = *(const float4*)(&s_hs[j][c0]);
#pragma unroll
            for (int r = 0; r < 4; r++) {
                float a = s_attn[i0 + 16 * r][j];
                acc[r][0] = fmaf(a, hv.x, acc[r][0]);
                acc[r][1] = fmaf(a, hv.y, acc[r][1]);
                acc[r][2] = fmaf(a, hv.z, acc[r][2]);
                acc[r][3] = fmaf(a, hv.w, acc[r][3]);
            }
        }

        float4 bv = *(const float4*)(bias + dc + c0);
#pragma unroll
        for (int r = 0; r < 4; r++) {
            float* orow = HOUT + (size_t)(i0 + 16 * r) * D + dc + c0;
            *(float4*)orow = make_float4(acc[r][0] + bv.x, acc[r][1] + bv.y,
                                         acc[r][2] + bv.z, acc[r][3] + bv.w);
        }
        __syncthreads();
    }
}

// ---------------------------------------------------------------------------
// final1: vec = [center(batch row0 feats), l2norm(h2[0])] into g_hp (512x1536)
// ---------------------------------------------------------------------------
__global__ __launch_bounds__(256) void final1_kernel(const float* __restrict__ batch) {
    const int b = blockIdx.x;
    const int tid = threadIdx.x;
    const int warp = tid >> 5, lane = tid & 31;
    __shared__ float red[8];

    const float* h0 = g_h + (size_t)b * NN * D;
    float ss = 0.f;
    for (int o = tid; o < D; o += 256) { float v = h0[o]; ss = fmaf(v, v, ss); }
#pragma unroll
    for (int off = 16; off; off >>= 1) ss += __shfl_xor_sync(0xffffffffu, ss, off);
    if (lane == 0) red[warp] = ss;
    __syncthreads();
    float tot = red[0];
#pragma unroll
    for (int w = 1; w < 8; w++) tot += red[w];
    float inv = 1.f / fmaxf(sqrtf(tot), 1e-12f);

    float* vec = g_hp + (size_t)b * 1536;
    const float* crow = batch + (size_t)b * NN * ROWSTRIDE;
    for (int o = tid; o < D; o += 256) {
        vec[o]     = crow[o];
        vec[D + o] = h0[o] * inv;
    }
}

// ---------------------------------------------------------------------------
// final2: 4 graphs per CTA, out[b] = l2norm(vec[b] @ mlp_w.T + mlp_b)
// ---------------------------------------------------------------------------
__global__ __launch_bounds__(256) void final2_kernel(const float* __restrict__ mlp_w,
                                                     const float* __restrict__ mlp_b,
                                                     float* __restrict__ out) {
    __shared__ float sv[4][1536];
    __shared__ float sout[4][768];
    const int b0 = blockIdx.x * 4;
    const int tid = threadIdx.x;
    const int warp = tid >> 5, lane = tid & 31;

    for (int t = tid; t < 4 * 384; t += 256) {
        int g = t / 384;
        int k4 = (t % 384) << 2;
        *(float4*)(&sv[g][k4]) = *(const float4*)(g_hp + (size_t)(b0 + g) * 1536 + k4);
    }
    __syncthreads();

    for (int o = warp; o < 768; o += 8) {
        const float* wr = mlp_w + (size_t)o * 1536;
        float a0 = 0.f, a1 = 0.f, a2 = 0.f, a3 = 0.f;
        for (int k4 = lane * 4; k4 < 1536; k4 += 128) {
            float4 wv = *(const float4*)(wr + k4);
            float4 x;
            x = *(const float4*)(&sv[0][k4]); a0 += wv.x*x.x + wv.y*x.y + wv.z*x.z + wv.w*x.w;
            x = *(const float4*)(&sv[1][k4]); a1 += wv.x*x.x + wv.y*x.y + wv.z*x.z + wv.w*x.w;
            x = *(const float4*)(&sv[2][k4]); a2 += wv.x*x.x + wv.y*x.y + wv.z*x.z + wv.w*x.w;
            x = *(const float4*)(&sv[3][k4]); a3 += wv.x*x.x + wv.y*x.y + wv.z*x.z + wv.w*x.w;
        }
#pragma unroll
        for (int off = 16; off; off >>= 1) {
            a0 += __shfl_xor_sync(0xffffffffu, a0, off);
            a1 += __shfl_xor_sync(0xffffffffu, a1, off);
            a2 += __shfl_xor_sync(0xffffffffu, a2, off);
            a3 += __shfl_xor_sync(0xffffffffu, a3, off);
        }
        if (lane == 0) {
            float bo = mlp_b[o];
            sout[0][o] = a0 + bo;
            sout[1][o] = a1 + bo;
            sout[2][o] = a2 + bo;
            sout[3][o] = a3 + bo;
        }
    }
    __syncthreads();

    if (warp < 4) {
        float ss = 0.f;
        for (int o = lane; o < 768; o += 32) { float v = sout[warp][o]; ss = fmaf(v, v, ss); }
#pragma unroll
        for (int off = 16; off; off >>= 1) ss += __shfl_xor_sync(0xffffffffu, ss, off);
        float inv = 1.f / fmaxf(sqrtf(ss), 1e-12f);
        for (int o = lane; o < 768; o += 32)
            out[(size_t)(b0 + warp) * 768 + o] = sout[warp][o] * inv;
    }
}

// ---------------------------------------------------------------------------
extern "C" void kernel_launch(void* const* d_in, const int* in_sizes, int n_in,
                              void* d_out, int out_size) {
    const float* batch = (const float*)d_in[0];
    const float* w     = (const float*)d_in[1];
    const float* a_src = (const float*)d_in[2];
    const float* a_dst = (const float*)d_in[3];
    const float* gbias = (const float*)d_in[4];
    const float* mlp_w = (const float*)d_in[5];
    const float* mlp_b = (const float*)d_in[6];
    float* out = (float*)d_out;

    dim3 gg(6, 256);  // 768/128 cols x 32768/128 rows
    gemm_tf32_kernel<<<gg, 256>>>(batch, 0, w);
    attn_kernel<<<512, 256>>>(batch, a_src, a_dst, gbias);
    gemm_tf32_kernel<<<gg, 256>>>(batch, 1, w);
    attn_kernel<<<512, 256>>>(batch, a_src, a_dst, gbias);
    final1_kernel<<<512, 256>>>(batch);
    final2_kernel<<<128, 256>>>(mlp_w, mlp_b, out);
}

// round 4
// speedup vs baseline: 3.3411x; 1.2754x over previous
#include <cuda_runtime.h>
#include <cuda_bf16.h>
#include <math.h>
#include <stdint.h>

#define D 768
#define NN 64
#define BS 512
#define ROWSTRIDE 832   // D + NN
#define NEG_SLOPE 0.2f

// Scratch (allocation-free rule: __device__ globals).
__device__ float g_hp[BS * NN * D];            // GEMM output / reused as concat-vec buffer
__device__ float g_h[BS * NN * D];             // attention output (next-layer input)
__device__ __nv_bfloat16 g_wt[D * D];          // W transposed to [n][k], bf16

__device__ __forceinline__ uint32_t smem_u32(const void* p) {
    uint32_t a;
    asm("{ .reg .u64 t; cvta.to.shared.u64 t, %1; cvt.u32.u64 %0, t; }" : "=r"(a) : "l"(p));
    return a;
}
__device__ __forceinline__ void ldsm_x4(uint32_t* r, uint32_t addr) {
    asm volatile("ldmatrix.sync.aligned.m8n8.x4.shared.b16 {%0,%1,%2,%3}, [%4];"
                 : "=r"(r[0]), "=r"(r[1]), "=r"(r[2]), "=r"(r[3]) : "r"(addr));
}
__device__ __forceinline__ void ldsm_x2(uint32_t* r, uint32_t addr) {
    asm volatile("ldmatrix.sync.aligned.m8n8.x2.shared.b16 {%0,%1}, [%2];"
                 : "=r"(r[0]), "=r"(r[1]) : "r"(addr));
}
__device__ __forceinline__ void mma_bf16(float* c, const uint32_t* a, const uint32_t* b) {
    asm volatile(
        "mma.sync.aligned.m16n8k16.row.col.f32.bf16.bf16.f32 "
        "{%0,%1,%2,%3}, {%4,%5,%6,%7}, {%8,%9}, {%0,%1,%2,%3};"
        : "+f"(c[0]), "+f"(c[1]), "+f"(c[2]), "+f"(c[3])
        : "r"(a[0]), "r"(a[1]), "r"(a[2]), "r"(a[3]), "r"(b[0]), "r"(b[1]));
}
__device__ __forceinline__ void cp_async16(uint32_t saddr, const void* g) {
    asm volatile("cp.async.cg.shared.global [%0], [%1], 16;" :: "r"(saddr), "l"(g) : "memory");
}

// ---------------------------------------------------------------------------
// W convert: g_wt[n][k] = bf16(W[k][n])
// ---------------------------------------------------------------------------
__global__ __launch_bounds__(256) void wconv_kernel(const float* __restrict__ W) {
    __shared__ float tile[32][33];
    const int n0 = blockIdx.x * 32, k0 = blockIdx.y * 32;
    const int tx = threadIdx.x & 31, ty = threadIdx.x >> 5;
#pragma unroll
    for (int i = ty; i < 32; i += 8)
        tile[i][tx] = W[(size_t)(k0 + i) * D + n0 + tx];
    __syncthreads();
#pragma unroll
    for (int i = ty; i < 32; i += 8)
        g_wt[(size_t)(n0 + i) * D + k0 + tx] = __float2bfloat16(tile[tx][i]);
}

// ---------------------------------------------------------------------------
// BF16 tensor-core GEMM (mma.sync + ldmatrix): g_hp = A @ W
// A (32768 x 768) fp32: layer 0 -> batch (lda=832), layer 1 -> g_h (lda=768)
// B from g_wt [n][k] bf16. CTA tile 128x128, BK=32, 256 thr = 8 warps (2m x 4n),
// warp tile 64x32. Double-buffered; A via reg prefetch+cvt, B via cp.async.
// ---------------------------------------------------------------------------
#define SA 40   // bf16 row stride (80 B): conflict-free ldmatrix
__global__ __launch_bounds__(256) void gemm_bf16_kernel(const float* __restrict__ batch,
                                                        int layer) {
    __shared__ __nv_bfloat16 As[2][128][SA];
    __shared__ __nv_bfloat16 Bs[2][128][SA];

    const float* A;
    int lda;
    if (layer == 0) { A = batch; lda = ROWSTRIDE; }
    else            { A = g_h;   lda = D; }

    const int tid  = threadIdx.x;
    const int bm   = blockIdx.y * 128;
    const int bn   = blockIdx.x * 128;
    const int wid  = tid >> 5;
    const int lane = tid & 31;
    const int wm   = (wid >> 2) * 64;
    const int wn   = (wid & 3) * 32;
    const int qr   = lane >> 2;
    const int qc   = lane & 3;

    // staging geometry
    const int ar = tid >> 3;            // A row 0..31 (x4 via +32*i? no: see below)
    // A: 4 float4/thread: idx = i*256+tid -> row idx>>3 (0..127), quad idx&7
    // B: 2 cp.async/thread: idx = i*256+tid -> row idx>>2 (0..127), 8-half chunk idx&3

    // ldmatrix base addresses (stage 0)
    const uint32_t a_base =
        smem_u32(&As[0][wm + (lane & 15)][(lane >> 4) * 8]);
    const uint32_t b_base =
        smem_u32(&Bs[0][wn + (lane & 7)][((lane >> 3) & 1) * 8]);
    const uint32_t ASTG = 128 * SA * 2;   // bytes per stage
    const uint32_t BSTG = 128 * SA * 2;

    float acc[4][4][4];
#pragma unroll
    for (int mi = 0; mi < 4; mi++)
#pragma unroll
        for (int ni = 0; ni < 4; ni++)
#pragma unroll
            for (int u = 0; u < 4; u++) acc[mi][ni][u] = 0.f;

    float4 pa[4];
    // prefetch chunk 0: A regs + B cp.async into stage 0
#pragma unroll
    for (int i = 0; i < 4; i++) {
        int idx = i * 256 + tid;
        pa[i] = *(const float4*)(A + (size_t)(bm + (idx >> 3)) * lda + (idx & 7) * 4);
    }
#pragma unroll
    for (int i = 0; i < 2; i++) {
        int idx = i * 256 + tid;
        int r = idx >> 2, c8 = (idx & 3) * 8;
        cp_async16(smem_u32(&Bs[0][r][c8]), g_wt + (size_t)(bn + r) * D + c8);
    }
    asm volatile("cp.async.commit_group;" ::: "memory");

#pragma unroll 1
    for (int t = 0; t < 24; t++) {
        const int s = t & 1;
        // stage A regs -> smem (cvt to bf16)
#pragma unroll
        for (int i = 0; i < 4; i++) {
            int idx = i * 256 + tid;
            int r = idx >> 3, q = idx & 7;
            __nv_bfloat162 lo = __floats2bfloat162_rn(pa[i].x, pa[i].y);
            __nv_bfloat162 hi = __floats2bfloat162_rn(pa[i].z, pa[i].w);
            uint2 pk;
            pk.x = *(uint32_t*)&lo;
            pk.y = *(uint32_t*)&hi;
            *(uint2*)(&As[s][r][q * 4]) = pk;
        }
        asm volatile("cp.async.wait_group 0;" ::: "memory");
        __syncthreads();

        // prefetch next chunk
        if (t + 1 < 24) {
            const int k0 = (t + 1) * 32;
#pragma unroll
            for (int i = 0; i < 4; i++) {
                int idx = i * 256 + tid;
                pa[i] = *(const float4*)(A + (size_t)(bm + (idx >> 3)) * lda + k0 + (idx & 7) * 4);
            }
#pragma unroll
            for (int i = 0; i < 2; i++) {
                int idx = i * 256 + tid;
                int r = idx >> 2, c8 = (idx & 3) * 8;
                cp_async16(smem_u32(&Bs[s ^ 1][r][c8]),
                           g_wt + (size_t)(bn + r) * D + k0 + c8);
            }
            asm volatile("cp.async.commit_group;" ::: "memory");
        }

        // compute this chunk: 2 k16-steps
#pragma unroll
        for (int ks = 0; ks < 2; ks++) {
            const uint32_t koff = ks * 32;  // 16 halves = 32 bytes
            uint32_t afr[4][4], bfr[4][2];
#pragma unroll
            for (int mi = 0; mi < 4; mi++)
                ldsm_x4(afr[mi], a_base + s * ASTG + mi * 16 * (SA * 2) + koff);
#pragma unroll
            for (int ni = 0; ni < 4; ni++)
                ldsm_x2(bfr[ni], b_base + s * BSTG + ni * 8 * (SA * 2) + koff);
#pragma unroll
            for (int mi = 0; mi < 4; mi++)
#pragma unroll
                for (int ni = 0; ni < 4; ni++)
                    mma_bf16(acc[mi][ni], afr[mi], bfr[ni]);
        }
    }

    // epilogue
#pragma unroll
    for (int mi = 0; mi < 4; mi++) {
#pragma unroll
        for (int ni = 0; ni < 4; ni++) {
            int row = bm + wm + mi * 16 + qr;
            int col = bn + wn + ni * 8 + qc * 2;
            *(float2*)(&g_hp[(size_t)row * D + col]) =
                make_float2(acc[mi][ni][0], acc[mi][ni][1]);
            *(float2*)(&g_hp[(size_t)(row + 8) * D + col]) =
                make_float2(acc[mi][ni][2], acc[mi][ni][3]);
        }
    }
}

// ---------------------------------------------------------------------------
// Attention: per graph (1 CTA, 256 thr). Reads g_hp, writes g_h.
// ---------------------------------------------------------------------------
__global__ __launch_bounds__(256) void attn_kernel(const float* __restrict__ batch,
                                                   const float* __restrict__ a_src,
                                                   const float* __restrict__ a_dst,
                                                   const float* __restrict__ bias) {
    __shared__ float s_attn[64][65];
    __shared__ float s_hs[64][68];
    __shared__ float s_src[64];
    __shared__ float s_dst[64];

    const int b = blockIdx.x;
    const int tid = threadIdx.x;
    const int warp = tid >> 5;
    const int lane = tid & 31;
    const float* HP = g_hp + (size_t)b * NN * D;

    for (int i = warp; i < NN; i += 8) {
        float s = 0.f, dd = 0.f;
        const float* hrow = HP + (size_t)i * D;
#pragma unroll
        for (int o4 = lane * 4; o4 < D; o4 += 128) {
            float4 h  = *(const float4*)(hrow + o4);
            float4 as = *(const float4*)(a_src + o4);
            float4 ad = *(const float4*)(a_dst + o4);
            float t0 = tanhf(h.x), t1 = tanhf(h.y), t2 = tanhf(h.z), t3 = tanhf(h.w);
            s  = fmaf(t0, as.x, fmaf(t1, as.y, fmaf(t2, as.z, fmaf(t3, as.w, s))));
            dd = fmaf(t0, ad.x, fmaf(t1, ad.y, fmaf(t2, ad.z, fmaf(t3, ad.w, dd))));
        }
#pragma unroll
        for (int off = 16; off; off >>= 1) {
            s  += __shfl_xor_sync(0xffffffffu, s, off);
            dd += __shfl_xor_sync(0xffffffffu, dd, off);
        }
        if (lane == 0) { s_src[i] = s; s_dst[i] = dd; }
    }
    __syncthreads();

    for (int i = warp; i < NN; i += 8) {
        const float* arow = batch + ((size_t)b * NN + i) * ROWSTRIDE + D;
        float e0, e1;
        {
            int j = lane;
            float v = s_src[i] + s_dst[j];
            v = (v >= 0.f) ? v : NEG_SLOPE * v;
            bool allowed = (arow[j] != 0.f) || (i == j);
            e0 = allowed ? v : -INFINITY;
        }
        {
            int j = lane + 32;
            float v = s_src[i] + s_dst[j];
            v = (v >= 0.f) ? v : NEG_SLOPE * v;
            bool allowed = (arow[j] != 0.f) || (i == j);
            e1 = allowed ? v : -INFINITY;
        }
        float mx = fmaxf(e0, e1);
#pragma unroll
        for (int off = 16; off; off >>= 1)
            mx = fmaxf(mx, __shfl_xor_sync(0xffffffffu, mx, off));
        float x0 = (e0 == -INFINITY) ? 0.f : __expf(e0 - mx);
        float x1 = (e1 == -INFINITY) ? 0.f : __expf(e1 - mx);
        float sum = x0 + x1;
#pragma unroll
        for (int off = 16; off; off >>= 1)
            sum += __shfl_xor_sync(0xffffffffu, sum, off);
        float inv = 1.f / sum;
        s_attn[i][lane]      = x0 * inv;
        s_attn[i][lane + 32] = x1 * inv;
    }
    __syncthreads();

    const int c0 = (tid & 15) * 4;
    const int i0 = tid >> 4;
    float* HOUT = g_h + (size_t)b * NN * D;

    for (int dc = 0; dc < D; dc += 64) {
        for (int t = tid; t < 64 * 16; t += 256) {
            int r = t >> 4;
            int c4 = (t & 15) << 2;
            *(float4*)(&s_hs[r][c4]) = *(const float4*)(HP + (size_t)r * D + dc + c4);
        }
        __syncthreads();

        float acc[4][4];
#pragma unroll
        for (int r = 0; r < 4; r++)
#pragma unroll
            for (int u = 0; u < 4; u++) acc[r][u] = 0.f;

#pragma unroll 4
        for (int j = 0; j < 64; j++) {
            float4 hv = *(const float4*)(&s_hs[j][c0]);
#pragma unroll
            for (int r = 0; r < 4; r++) {
                float a = s_attn[i0 + 16 * r][j];
                acc[r][0] = fmaf(a, hv.x, acc[r][0]);
                acc[r][1] = fmaf(a, hv.y, acc[r][1]);
                acc[r][2] = fmaf(a, hv.z, acc[r][2]);
                acc[r][3] = fmaf(a, hv.w, acc[r][3]);
            }
        }

        float4 bv = *(const float4*)(bias + dc + c0);
#pragma unroll
        for (int r = 0; r < 4; r++) {
            float* orow = HOUT + (size_t)(i0 + 16 * r) * D + dc + c0;
            *(float4*)orow = make_float4(acc[r][0] + bv.x, acc[r][1] + bv.y,
                                         acc[r][2] + bv.z, acc[r][3] + bv.w);
        }
        __syncthreads();
    }
}

// ---------------------------------------------------------------------------
__global__ __launch_bounds__(256) void final1_kernel(const float* __restrict__ batch) {
    const int b = blockIdx.x;
    const int tid = threadIdx.x;
    const int warp = tid >> 5, lane = tid & 31;
    __shared__ float red[8];

    const float* h0 = g_h + (size_t)b * NN * D;
    float ss = 0.f;
    for (int o = tid; o < D; o += 256) { float v = h0[o]; ss = fmaf(v, v, ss); }
#pragma unroll
    for (int off = 16; off; off >>= 1) ss += __shfl_xor_sync(0xffffffffu, ss, off);
    if (lane == 0) red[warp] = ss;
    __syncthreads();
    float tot = red[0];
#pragma unroll
    for (int w = 1; w < 8; w++) tot += red[w];
    float inv = 1.f / fmaxf(sqrtf(tot), 1e-12f);

    float* vec = g_hp + (size_t)b * 1536;
    const float* crow = batch + (size_t)b * NN * ROWSTRIDE;
    for (int o = tid; o < D; o += 256) {
        vec[o]     = crow[o];
        vec[D + o] = h0[o] * inv;
    }
}

// ---------------------------------------------------------------------------
__global__ __launch_bounds__(256) void final2_kernel(const float* __restrict__ mlp_w,
                                                     const float* __restrict__ mlp_b,
                                                     float* __restrict__ out) {
    __shared__ float sv[4][1536];
    __shared__ float sout[4][768];
    const int b0 = blockIdx.x * 4;
    const int tid = threadIdx.x;
    const int warp = tid >> 5, lane = tid & 31;

    for (int t = tid; t < 4 * 384; t += 256) {
        int g = t / 384;
        int k4 = (t % 384) << 2;
        *(float4*)(&sv[g][k4]) = *(const float4*)(g_hp + (size_t)(b0 + g) * 1536 + k4);
    }
    __syncthreads();

    for (int o = warp; o < 768; o += 8) {
        const float* wr = mlp_w + (size_t)o * 1536;
        float a0 = 0.f, a1 = 0.f, a2 = 0.f, a3 = 0.f;
        for (int k4 = lane * 4; k4 < 1536; k4 += 128) {
            float4 wv = *(const float4*)(wr + k4);
            float4 x;
            x = *(const float4*)(&sv[0][k4]); a0 += wv.x*x.x + wv.y*x.y + wv.z*x.z + wv.w*x.w;
            x = *(const float4*)(&sv[1][k4]); a1 += wv.x*x.x + wv.y*x.y + wv.z*x.z + wv.w*x.w;
            x = *(const float4*)(&sv[2][k4]); a2 += wv.x*x.x + wv.y*x.y + wv.z*x.z + wv.w*x.w;
            x = *(const float4*)(&sv[3][k4]); a3 += wv.x*x.x + wv.y*x.y + wv.z*x.z + wv.w*x.w;
        }
#pragma unroll
        for (int off = 16; off; off >>= 1) {
            a0 += __shfl_xor_sync(0xffffffffu, a0, off);
            a1 += __shfl_xor_sync(0xffffffffu, a1, off);
            a2 += __shfl_xor_sync(0xffffffffu, a2, off);
            a3 += __shfl_xor_sync(0xffffffffu, a3, off);
        }
        if (lane == 0) {
            float bo = mlp_b[o];
            sout[0][o] = a0 + bo;
            sout[1][o] = a1 + bo;
            sout[2][o] = a2 + bo;
            sout[3][o] = a3 + bo;
        }
    }
    __syncthreads();

    if (warp < 4) {
        float ss = 0.f;
        for (int o = lane; o < 768; o += 32) { float v = sout[warp][o]; ss = fmaf(v, v, ss); }
#pragma unroll
        for (int off = 16; off; off >>= 1) ss += __shfl_xor_sync(0xffffffffu, ss, off);
        float inv = 1.f / fmaxf(sqrtf(ss), 1e-12f);
        for (int o = lane; o < 768; o += 32)
            out[(size_t)(b0 + warp) * 768 + o] = sout[warp][o] * inv;
    }
}

// ---------------------------------------------------------------------------
extern "C" void kernel_launch(void* const* d_in, const int* in_sizes, int n_in,
                              void* d_out, int out_size) {
    const float* batch = (const float*)d_in[0];
    const float* w     = (const float*)d_in[1];
    const float* a_src = (const float*)d_in[2];
    const float* a_dst = (const float*)d_in[3];
    const float* gbias = (const float*)d_in[4];
    const float* mlp_w = (const float*)d_in[5];
    const float* mlp_b = (const float*)d_in[6];
    float* out = (float*)d_out;

    wconv_kernel<<<dim3(24, 24), 256>>>(w);
    dim3 gg(6, 256);
    gemm_bf16_kernel<<<gg, 256>>>(batch, 0);
    attn_kernel<<<512, 256>>>(batch, a_src, a_dst, gbias);
    gemm_bf16_kernel<<<gg, 256>>>(batch, 1);
    attn_kernel<<<512, 256>>>(batch, a_src, a_dst, gbias);
    final1_kernel<<<512, 256>>>(batch);
    final2_kernel<<<128, 256>>>(mlp_w, mlp_b, out);
}

// round 5
// speedup vs baseline: 3.5504x; 1.0626x over previous
#include <cuda_runtime.h>
#include <cuda_bf16.h>
#include <math.h>
#include <stdint.h>

#define D 768
#define NN 64
#define BS 512
#define ROWSTRIDE 832   // D + NN
#define NEG_SLOPE 0.2f

// Scratch (allocation-free rule: __device__ globals).
__device__ float g_hp[BS * NN * D];            // GEMM output fp32 / reused as concat buffer
__device__ __nv_bfloat16 g_ab[BS * NN * D];    // GEMM input A, bf16
__device__ float g_h0[BS * D];                 // attn output row 0 (fp32, for head)
__device__ __nv_bfloat16 g_wt[D * D];          // W transposed to [n][k], bf16

__device__ __forceinline__ uint32_t smem_u32(const void* p) {
    uint32_t a;
    asm("{ .reg .u64 t; cvta.to.shared.u64 t, %1; cvt.u32.u64 %0, t; }" : "=r"(a) : "l"(p));
    return a;
}
__device__ __forceinline__ void ldsm_x4(uint32_t* r, uint32_t addr) {
    asm volatile("ldmatrix.sync.aligned.m8n8.x4.shared.b16 {%0,%1,%2,%3}, [%4];"
                 : "=r"(r[0]), "=r"(r[1]), "=r"(r[2]), "=r"(r[3]) : "r"(addr));
}
__device__ __forceinline__ void ldsm_x2(uint32_t* r, uint32_t addr) {
    asm volatile("ldmatrix.sync.aligned.m8n8.x2.shared.b16 {%0,%1}, [%2];"
                 : "=r"(r[0]), "=r"(r[1]) : "r"(addr));
}
__device__ __forceinline__ void mma_bf16(float* c, const uint32_t* a, const uint32_t* b) {
    asm volatile(
        "mma.sync.aligned.m16n8k16.row.col.f32.bf16.bf16.f32 "
        "{%0,%1,%2,%3}, {%4,%5,%6,%7}, {%8,%9}, {%0,%1,%2,%3};"
        : "+f"(c[0]), "+f"(c[1]), "+f"(c[2]), "+f"(c[3])
        : "r"(a[0]), "r"(a[1]), "r"(a[2]), "r"(a[3]), "r"(b[0]), "r"(b[1]));
}
__device__ __forceinline__ void cp_async16(uint32_t saddr, const void* g) {
    asm volatile("cp.async.cg.shared.global [%0], [%1], 16;" :: "r"(saddr), "l"(g) : "memory");
}
__device__ __forceinline__ float tanhap(float x) {
    float y; asm("tanh.approx.f32 %0, %1;" : "=f"(y) : "f"(x)); return y;
}

// ---------------------------------------------------------------------------
// W convert: g_wt[n][k] = bf16(W[k][n])
// ---------------------------------------------------------------------------
__global__ __launch_bounds__(256) void wconv_kernel(const float* __restrict__ W) {
    __shared__ float tile[32][33];
    const int n0 = blockIdx.x * 32, k0 = blockIdx.y * 32;
    const int tx = threadIdx.x & 31, ty = threadIdx.x >> 5;
#pragma unroll
    for (int i = ty; i < 32; i += 8)
        tile[i][tx] = W[(size_t)(k0 + i) * D + n0 + tx];
    __syncthreads();
#pragma unroll
    for (int i = ty; i < 32; i += 8)
        g_wt[(size_t)(n0 + i) * D + k0 + tx] = __float2bfloat16(tile[tx][i]);
}

// ---------------------------------------------------------------------------
// A convert (layer 0): g_ab = bf16(batch features), strided 832 -> dense 768
// ---------------------------------------------------------------------------
__global__ __launch_bounds__(256) void aconv_kernel(const float* __restrict__ batch) {
    const int b = blockIdx.x;
    const float* src = batch + (size_t)b * NN * ROWSTRIDE;
    __nv_bfloat16* dst = g_ab + (size_t)b * NN * D;
    for (int idx = threadIdx.x; idx < NN * (D / 4); idx += 256) {
        int row = idx / (D / 4);
        int q = (idx % (D / 4)) * 4;
        float4 v = *(const float4*)(src + (size_t)row * ROWSTRIDE + q);
        __nv_bfloat162 lo = __floats2bfloat162_rn(v.x, v.y);
        __nv_bfloat162 hi = __floats2bfloat162_rn(v.z, v.w);
        uint2 pk;
        pk.x = *(uint32_t*)&lo;
        pk.y = *(uint32_t*)&hi;
        *(uint2*)(dst + (size_t)row * D + q) = pk;
    }
}

// ---------------------------------------------------------------------------
// BF16 tensor-core GEMM: g_hp = g_ab @ g_wt^T  (both bf16, fp32 accum)
// CTA tile 128x128, BK=64, 2-stage cp.async pipeline, 256 thr = 8 warps (2m x 4n).
// smem row stride 72 halves (144 B): conflict-free ldmatrix + cp.async.
// ---------------------------------------------------------------------------
#define GBK 64
#define GSA 72                       // halves per smem row
#define GSTAGE 36864                 // bytes per stage: 2 tiles * 128*72*2
#define GSMEM  (2 * GSTAGE)

__global__ __launch_bounds__(256) void gemm_bf16_kernel() {
    extern __shared__ char smem[];
    const uint32_t sb = smem_u32(smem);

    const int tid  = threadIdx.x;
    const int wid  = tid >> 5;
    const int lane = tid & 31;
    const int bm   = blockIdx.y * 128;
    const int bn   = blockIdx.x * 128;
    const int wm   = (wid >> 2) * 64;
    const int wn   = (wid & 3) * 32;
    const int qr   = lane >> 2;
    const int qc   = lane & 3;

    // per-thread cp.async geometry: 4 granules per tile
    int lrow[4], lc8[4];
#pragma unroll
    for (int i = 0; i < 4; i++) {
        int idx = i * 256 + tid;
        lrow[i] = idx >> 3;
        lc8[i]  = (idx & 7) * 8;
    }

    // ldmatrix bases (within a stage)
    const uint32_t a_off = (uint32_t)(((wm + (lane & 15)) * GSA + (lane >> 4) * 8) * 2);
    const uint32_t b_off = (uint32_t)(((wn + (lane & 7)) * GSA + ((lane >> 3) & 1) * 8) * 2);

    float acc[4][4][4];
#pragma unroll
    for (int mi = 0; mi < 4; mi++)
#pragma unroll
        for (int ni = 0; ni < 4; ni++)
#pragma unroll
            for (int u = 0; u < 4; u++) acc[mi][ni][u] = 0.f;

    // issue chunk t into stage s
    auto issue = [&](int t, int s) {
        const int k0 = t * GBK;
        const uint32_t abase = sb + (uint32_t)s * GSTAGE;
        const uint32_t bbase = abase + 18432;
#pragma unroll
        for (int i = 0; i < 4; i++)
            cp_async16(abase + (uint32_t)((lrow[i] * GSA + lc8[i]) * 2),
                       g_ab + (size_t)(bm + lrow[i]) * D + k0 + lc8[i]);
#pragma unroll
        for (int i = 0; i < 4; i++)
            cp_async16(bbase + (uint32_t)((lrow[i] * GSA + lc8[i]) * 2),
                       g_wt + (size_t)(bn + lrow[i]) * D + k0 + lc8[i]);
        asm volatile("cp.async.commit_group;" ::: "memory");
    };

    issue(0, 0);
    issue(1, 1);

#pragma unroll 1
    for (int t = 0; t < 12; t++) {
        const int s = t & 1;
        if (t < 10) asm volatile("cp.async.wait_group 1;" ::: "memory");
        else        asm volatile("cp.async.wait_group 0;" ::: "memory");
        __syncthreads();

        const uint32_t abase = sb + (uint32_t)s * GSTAGE + a_off;
        const uint32_t bbase = sb + (uint32_t)s * GSTAGE + 18432 + b_off;
#pragma unroll
        for (int ks = 0; ks < 4; ks++) {
            const uint32_t koff = ks * 32;  // 16 halves
            uint32_t afr[4][4], bfr[4][2];
#pragma unroll
            for (int mi = 0; mi < 4; mi++)
                ldsm_x4(afr[mi], abase + mi * 16 * (GSA * 2) + koff);
#pragma unroll
            for (int ni = 0; ni < 4; ni++)
                ldsm_x2(bfr[ni], bbase + ni * 8 * (GSA * 2) + koff);
#pragma unroll
            for (int mi = 0; mi < 4; mi++)
#pragma unroll
                for (int ni = 0; ni < 4; ni++)
                    mma_bf16(acc[mi][ni], afr[mi], bfr[ni]);
        }
        __syncthreads();
        if (t + 2 < 12) issue(t + 2, s);
    }

    // epilogue: fp32 to g_hp
#pragma unroll
    for (int mi = 0; mi < 4; mi++) {
#pragma unroll
        for (int ni = 0; ni < 4; ni++) {
            int row = bm + wm + mi * 16 + qr;
            int col = bn + wn + ni * 8 + qc * 2;
            *(float2*)(&g_hp[(size_t)row * D + col]) =
                make_float2(acc[mi][ni][0], acc[mi][ni][1]);
            *(float2*)(&g_hp[(size_t)(row + 8) * D + col]) =
                make_float2(acc[mi][ni][2], acc[mi][ni][3]);
        }
    }
}

// ---------------------------------------------------------------------------
// Attention: per graph (1 CTA, 256 thr). Reads g_hp (fp32), writes g_ab (bf16)
// and g_h0 (fp32 row 0).
// ---------------------------------------------------------------------------
__global__ __launch_bounds__(256) void attn_kernel(const float* __restrict__ batch,
                                                   const float* __restrict__ a_src,
                                                   const float* __restrict__ a_dst,
                                                   const float* __restrict__ bias) {
    __shared__ float s_attn[64][65];
    __shared__ float s_hs[64][68];
    __shared__ float s_src[64];
    __shared__ float s_dst[64];

    const int b = blockIdx.x;
    const int tid = threadIdx.x;
    const int warp = tid >> 5;
    const int lane = tid & 31;
    const float* HP = g_hp + (size_t)b * NN * D;

    // ---- 1. src/dst row dots (tanh.approx) ----
    for (int i = warp; i < NN; i += 8) {
        float s = 0.f, dd = 0.f;
        const float* hrow = HP + (size_t)i * D;
#pragma unroll
        for (int o4 = lane * 4; o4 < D; o4 += 128) {
            float4 h  = *(const float4*)(hrow + o4);
            float4 as = *(const float4*)(a_src + o4);
            float4 ad = *(const float4*)(a_dst + o4);
            float t0 = tanhap(h.x), t1 = tanhap(h.y), t2 = tanhap(h.z), t3 = tanhap(h.w);
            s  = fmaf(t0, as.x, fmaf(t1, as.y, fmaf(t2, as.z, fmaf(t3, as.w, s))));
            dd = fmaf(t0, ad.x, fmaf(t1, ad.y, fmaf(t2, ad.z, fmaf(t3, ad.w, dd))));
        }
#pragma unroll
        for (int off = 16; off; off >>= 1) {
            s  += __shfl_xor_sync(0xffffffffu, s, off);
            dd += __shfl_xor_sync(0xffffffffu, dd, off);
        }
        if (lane == 0) { s_src[i] = s; s_dst[i] = dd; }
    }
    __syncthreads();

    // ---- 2. scores + softmax ----
    for (int i = warp; i < NN; i += 8) {
        const float* arow = batch + ((size_t)b * NN + i) * ROWSTRIDE + D;
        float e0, e1;
        {
            int j = lane;
            float v = s_src[i] + s_dst[j];
            v = (v >= 0.f) ? v : NEG_SLOPE * v;
            bool allowed = (arow[j] != 0.f) || (i == j);
            e0 = allowed ? v : -INFINITY;
        }
        {
            int j = lane + 32;
            float v = s_src[i] + s_dst[j];
            v = (v >= 0.f) ? v : NEG_SLOPE * v;
            bool allowed = (arow[j] != 0.f) || (i == j);
            e1 = allowed ? v : -INFINITY;
        }
        float mx = fmaxf(e0, e1);
#pragma unroll
        for (int off = 16; off; off >>= 1)
            mx = fmaxf(mx, __shfl_xor_sync(0xffffffffu, mx, off));
        float x0 = (e0 == -INFINITY) ? 0.f : __expf(e0 - mx);
        float x1 = (e1 == -INFINITY) ? 0.f : __expf(e1 - mx);
        float sum = x0 + x1;
#pragma unroll
        for (int off = 16; off; off >>= 1)
            sum += __shfl_xor_sync(0xffffffffu, sum, off);
        float inv = 1.f / sum;
        s_attn[i][lane]      = x0 * inv;
        s_attn[i][lane + 32] = x1 * inv;
    }
    __syncthreads();

    // ---- 3. out = attn @ hp + bias -> bf16 g_ab (+ fp32 row 0 -> g_h0) ----
    const int c0 = (tid & 15) * 4;
    const int i0 = tid >> 4;
    __nv_bfloat16* AOUT = g_ab + (size_t)b * NN * D;

    for (int dc = 0; dc < D; dc += 64) {
        for (int t = tid; t < 64 * 16; t += 256) {
            int r = t >> 4;
            int c4 = (t & 15) << 2;
            *(float4*)(&s_hs[r][c4]) = *(const float4*)(HP + (size_t)r * D + dc + c4);
        }
        __syncthreads();

        float acc[4][4];
#pragma unroll
        for (int r = 0; r < 4; r++)
#pragma unroll
            for (int u = 0; u < 4; u++) acc[r][u] = 0.f;

#pragma unroll 4
        for (int j = 0; j < 64; j++) {
            float4 hv = *(const float4*)(&s_hs[j][c0]);
#pragma unroll
            for (int r = 0; r < 4; r++) {
                float a = s_attn[i0 + 16 * r][j];
                acc[r][0] = fmaf(a, hv.x, acc[r][0]);
                acc[r][1] = fmaf(a, hv.y, acc[r][1]);
                acc[r][2] = fmaf(a, hv.z, acc[r][2]);
                acc[r][3] = fmaf(a, hv.w, acc[r][3]);
            }
        }

        float4 bv = *(const float4*)(bias + dc + c0);
#pragma unroll
        for (int r = 0; r < 4; r++) {
            int row = i0 + 16 * r;
            float v0 = acc[r][0] + bv.x, v1 = acc[r][1] + bv.y;
            float v2 = acc[r][2] + bv.z, v3 = acc[r][3] + bv.w;
            __nv_bfloat162 lo = __floats2bfloat162_rn(v0, v1);
            __nv_bfloat162 hi = __floats2bfloat162_rn(v2, v3);
            uint2 pk;
            pk.x = *(uint32_t*)&lo;
            pk.y = *(uint32_t*)&hi;
            *(uint2*)(AOUT + (size_t)row * D + dc + c0) = pk;
            if (row == 0)
                *(float4*)(g_h0 + (size_t)b * D + dc + c0) = make_float4(v0, v1, v2, v3);
        }
        __syncthreads();
    }
}

// ---------------------------------------------------------------------------
// final1: vec = [center(batch row0 feats), l2norm(g_h0[b])] into g_hp (512x1536)
// ---------------------------------------------------------------------------
__global__ __launch_bounds__(256) void final1_kernel(const float* __restrict__ batch) {
    const int b = blockIdx.x;
    const int tid = threadIdx.x;
    const int warp = tid >> 5, lane = tid & 31;
    __shared__ float red[8];

    const float* h0 = g_h0 + (size_t)b * D;
    float ss = 0.f;
    for (int o = tid; o < D; o += 256) { float v = h0[o]; ss = fmaf(v, v, ss); }
#pragma unroll
    for (int off = 16; off; off >>= 1) ss += __shfl_xor_sync(0xffffffffu, ss, off);
    if (lane == 0) red[warp] = ss;
    __syncthreads();
    float tot = red[0];
#pragma unroll
    for (int w = 1; w < 8; w++) tot += red[w];
    float inv = 1.f / fmaxf(sqrtf(tot), 1e-12f);

    float* vec = g_hp + (size_t)b * 1536;
    const float* crow = batch + (size_t)b * NN * ROWSTRIDE;
    for (int o = tid; o < D; o += 256) {
        vec[o]     = crow[o];
        vec[D + o] = h0[o] * inv;
    }
}

// ---------------------------------------------------------------------------
// final2: 4 graphs per CTA, out[b] = l2norm(vec[b] @ mlp_w.T + mlp_b)
// ---------------------------------------------------------------------------
__global__ __launch_bounds__(256) void final2_kernel(const float* __restrict__ mlp_w,
                                                     const float* __restrict__ mlp_b,
                                                     float* __restrict__ out) {
    __shared__ float sv[4][1536];
    __shared__ float sout[4][768];
    const int b0 = blockIdx.x * 4;
    const int tid = threadIdx.x;
    const int warp = tid >> 5, lane = tid & 31;

    for (int t = tid; t < 4 * 384; t += 256) {
        int g = t / 384;
        int k4 = (t % 384) << 2;
        *(float4*)(&sv[g][k4]) = *(const float4*)(g_hp + (size_t)(b0 + g) * 1536 + k4);
    }
    __syncthreads();

    for (int o = warp; o < 768; o += 8) {
        const float* wr = mlp_w + (size_t)o * 1536;
        float a0 = 0.f, a1 = 0.f, a2 = 0.f, a3 = 0.f;
        for (int k4 = lane * 4; k4 < 1536; k4 += 128) {
            float4 wv = *(const float4*)(wr + k4);
            float4 x;
            x = *(const float4*)(&sv[0][k4]); a0 += wv.x*x.x + wv.y*x.y + wv.z*x.z + wv.w*x.w;
            x = *(const float4*)(&sv[1][k4]); a1 += wv.x*x.x + wv.y*x.y + wv.z*x.z + wv.w*x.w;
            x = *(const float4*)(&sv[2][k4]); a2 += wv.x*x.x + wv.y*x.y + wv.z*x.z + wv.w*x.w;
            x = *(const float4*)(&sv[3][k4]); a3 += wv.x*x.x + wv.y*x.y + wv.z*x.z + wv.w*x.w;
        }
#pragma unroll
        for (int off = 16; off; off >>= 1) {
            a0 += __shfl_xor_sync(0xffffffffu, a0, off);
            a1 += __shfl_xor_sync(0xffffffffu, a1, off);
            a2 += __shfl_xor_sync(0xffffffffu, a2, off);
            a3 += __shfl_xor_sync(0xffffffffu, a3, off);
        }
        if (lane == 0) {
            float bo = mlp_b[o];
            sout[0][o] = a0 + bo;
            sout[1][o] = a1 + bo;
            sout[2][o] = a2 + bo;
            sout[3][o] = a3 + bo;
        }
    }
    __syncthreads();

    if (warp < 4) {
        float ss = 0.f;
        for (int o = lane; o < 768; o += 32) { float v = sout[warp][o]; ss = fmaf(v, v, ss); }
#pragma unroll
        for (int off = 16; off; off >>= 1) ss += __shfl_xor_sync(0xffffffffu, ss, off);
        float inv = 1.f / fmaxf(sqrtf(ss), 1e-12f);
        for (int o = lane; o < 768; o += 32)
            out[(size_t)(b0 + warp) * 768 + o] = sout[warp][o] * inv;
    }
}

// ---------------------------------------------------------------------------
extern "C" void kernel_launch(void* const* d_in, const int* in_sizes, int n_in,
                              void* d_out, int out_size) {
    const float* batch = (const float*)d_in[0];
    const float* w     = (const float*)d_in[1];
    const float* a_src = (const float*)d_in[2];
    const float* a_dst = (const float*)d_in[3];
    const float* gbias = (const float*)d_in[4];
    const float* mlp_w = (const float*)d_in[5];
    const float* mlp_b = (const float*)d_in[6];
    float* out = (float*)d_out;

    cudaFuncSetAttribute(gemm_bf16_kernel,
                         cudaFuncAttributeMaxDynamicSharedMemorySize, GSMEM);

    wconv_kernel<<<dim3(24, 24), 256>>>(w);
    aconv_kernel<<<512, 256>>>(batch);
    dim3 gg(6, 256);
    gemm_bf16_kernel<<<gg, 256, GSMEM>>>();
    attn_kernel<<<512, 256>>>(batch, a_src, a_dst, gbias);
    gemm_bf16_kernel<<<gg, 256, GSMEM>>>();
    attn_kernel<<<512, 256>>>(batch, a_src, a_dst, gbias);
    final1_kernel<<<512, 256>>>(batch);
    final2_kernel<<<128, 256>>>(mlp_w, mlp_b, out);
}

// round 7
// speedup vs baseline: 4.0238x; 1.1333x over previous
#include <cuda_runtime.h>
#include <cuda_bf16.h>
#include <math.h>
#include <stdint.h>

#define D 768
#define NN 64
#define BS 512
#define ROWSTRIDE 832   // D + NN
#define NEG_SLOPE 0.2f

// Scratch (allocation-free rule: __device__ globals).
__device__ float g_hp[BS * NN * D];            // fp32 GEMM out / concat buffer (512x1536)
__device__ __nv_bfloat16 g_ab[BS * NN * D];    // bf16 GEMM input A
__device__ float g_h0[BS * D];                 // attn row-0 output fp32
__device__ __nv_bfloat16 g_wt[D * D];          // W^T bf16 [n][k]

__device__ __forceinline__ uint32_t smem_u32(const void* p) {
    uint32_t a;
    asm("{ .reg .u64 t; cvta.to.shared.u64 t, %1; cvt.u32.u64 %0, t; }" : "=r"(a) : "l"(p));
    return a;
}
__device__ __forceinline__ void ldsm_x4(uint32_t* r, uint32_t addr) {
    asm volatile("ldmatrix.sync.aligned.m8n8.x4.shared.b16 {%0,%1,%2,%3}, [%4];"
                 : "=r"(r[0]), "=r"(r[1]), "=r"(r[2]), "=r"(r[3]) : "r"(addr));
}
__device__ __forceinline__ void ldsm_x2(uint32_t* r, uint32_t addr) {
    asm volatile("ldmatrix.sync.aligned.m8n8.x2.shared.b16 {%0,%1}, [%2];"
                 : "=r"(r[0]), "=r"(r[1]) : "r"(addr));
}
__device__ __forceinline__ void mma_bf16(float* c, const uint32_t* a, const uint32_t* b) {
    asm volatile(
        "mma.sync.aligned.m16n8k16.row.col.f32.bf16.bf16.f32 "
        "{%0,%1,%2,%3}, {%4,%5,%6,%7}, {%8,%9}, {%0,%1,%2,%3};"
        : "+f"(c[0]), "+f"(c[1]), "+f"(c[2]), "+f"(c[3])
        : "r"(a[0]), "r"(a[1]), "r"(a[2]), "r"(a[3]), "r"(b[0]), "r"(b[1]));
}
__device__ __forceinline__ void mma_tf32(float* c, const float* a, const float* b) {
    asm volatile(
        "mma.sync.aligned.m16n8k8.row.col.f32.tf32.tf32.f32 "
        "{%0,%1,%2,%3}, {%4,%5,%6,%7}, {%8,%9}, {%0,%1,%2,%3};"
        : "+f"(c[0]), "+f"(c[1]), "+f"(c[2]), "+f"(c[3])
        : "r"(__float_as_uint(a[0])), "r"(__float_as_uint(a[1])),
          "r"(__float_as_uint(a[2])), "r"(__float_as_uint(a[3])),
          "r"(__float_as_uint(b[0])), "r"(__float_as_uint(b[1])));
}
__device__ __forceinline__ void cp_async16(uint32_t saddr, const void* g) {
    asm volatile("cp.async.cg.shared.global [%0], [%1], 16;" :: "r"(saddr), "l"(g) : "memory");
}
__device__ __forceinline__ float tanhap(float x) {
    float y; asm("tanh.approx.f32 %0, %1;" : "=f"(y) : "f"(x)); return y;
}
__device__ __forceinline__ float tf32r(float x) {
    uint32_t u;
    asm("cvt.rna.tf32.f32 %0, %1;" : "=r"(u) : "f"(x));
    return __uint_as_float(u);
}

// ---------------------------------------------------------------------------
// W convert: g_wt[n][k] = bf16(W[k][n])
// ---------------------------------------------------------------------------
__global__ __launch_bounds__(256) void wconv_kernel(const float* __restrict__ W) {
    __shared__ float tile[32][33];
    const int n0 = blockIdx.x * 32, k0 = blockIdx.y * 32;
    const int tx = threadIdx.x & 31, ty = threadIdx.x >> 5;
#pragma unroll
    for (int i = ty; i < 32; i += 8)
        tile[i][tx] = W[(size_t)(k0 + i) * D + n0 + tx];
    __syncthreads();
#pragma unroll
    for (int i = ty; i < 32; i += 8)
        g_wt[(size_t)(n0 + i) * D + k0 + tx] = __float2bfloat16(tile[tx][i]);
}

// ---------------------------------------------------------------------------
// A convert (layer 0): g_ab = bf16(batch features), strided 832 -> dense 768
// ---------------------------------------------------------------------------
__global__ __launch_bounds__(256) void aconv_kernel(const float* __restrict__ batch) {
    const int b = blockIdx.x;
    const float* src = batch + (size_t)b * NN * ROWSTRIDE;
    __nv_bfloat16* dst = g_ab + (size_t)b * NN * D;
    for (int idx = threadIdx.x; idx < NN * (D / 4); idx += 256) {
        int row = idx / (D / 4);
        int q = (idx % (D / 4)) * 4;
        float4 v = *(const float4*)(src + (size_t)row * ROWSTRIDE + q);
        __nv_bfloat162 lo = __floats2bfloat162_rn(v.x, v.y);
        __nv_bfloat162 hi = __floats2bfloat162_rn(v.z, v.w);
        uint2 pk;
        pk.x = *(uint32_t*)&lo;
        pk.y = *(uint32_t*)&hi;
        *(uint2*)(dst + (size_t)row * D + q) = pk;
    }
}

// ---------------------------------------------------------------------------
// BF16 tensor-core GEMM: g_hp = g_ab @ g_wt^T (tf32-rounded outputs)
// CTA tile 128x128, BK=64, 2-stage cp.async, 8 warps (2m x 4n).
// ---------------------------------------------------------------------------
#define GSA 72
#define GSTAGE 36864
#define GSMEM  (2 * GSTAGE)

__global__ __launch_bounds__(256) void gemm_bf16_kernel() {
    extern __shared__ char smem[];
    const uint32_t sb = smem_u32(smem);

    const int tid  = threadIdx.x;
    const int wid  = tid >> 5;
    const int lane = tid & 31;
    const int bm   = blockIdx.y * 128;
    const int bn   = blockIdx.x * 128;
    const int wm   = (wid >> 2) * 64;
    const int wn   = (wid & 3) * 32;
    const int qr   = lane >> 2;
    const int qc   = lane & 3;

    int lrow[4], lc8[4];
#pragma unroll
    for (int i = 0; i < 4; i++) {
        int idx = i * 256 + tid;
        lrow[i] = idx >> 3;
        lc8[i]  = (idx & 7) * 8;
    }

    const uint32_t a_off = (uint32_t)(((wm + (lane & 15)) * GSA + (lane >> 4) * 8) * 2);
    const uint32_t b_off = (uint32_t)(((wn + (lane & 7)) * GSA + ((lane >> 3) & 1) * 8) * 2);

    float acc[4][4][4];
#pragma unroll
    for (int mi = 0; mi < 4; mi++)
#pragma unroll
        for (int ni = 0; ni < 4; ni++)
#pragma unroll
            for (int u = 0; u < 4; u++) acc[mi][ni][u] = 0.f;

    auto issue = [&](int t, int s) {
        const int k0 = t * 64;
        const uint32_t abase = sb + (uint32_t)s * GSTAGE;
        const uint32_t bbase = abase + 18432;
#pragma unroll
        for (int i = 0; i < 4; i++)
            cp_async16(abase + (uint32_t)((lrow[i] * GSA + lc8[i]) * 2),
                       g_ab + (size_t)(bm + lrow[i]) * D + k0 + lc8[i]);
#pragma unroll
        for (int i = 0; i < 4; i++)
            cp_async16(bbase + (uint32_t)((lrow[i] * GSA + lc8[i]) * 2),
                       g_wt + (size_t)(bn + lrow[i]) * D + k0 + lc8[i]);
        asm volatile("cp.async.commit_group;" ::: "memory");
    };

    issue(0, 0);
    issue(1, 1);

#pragma unroll 1
    for (int t = 0; t < 12; t++) {
        const int s = t & 1;
        if (t < 10) asm volatile("cp.async.wait_group 1;" ::: "memory");
        else        asm volatile("cp.async.wait_group 0;" ::: "memory");
        __syncthreads();

        const uint32_t abase = sb + (uint32_t)s * GSTAGE + a_off;
        const uint32_t bbase = sb + (uint32_t)s * GSTAGE + 18432 + b_off;
#pragma unroll
        for (int ks = 0; ks < 4; ks++) {
            const uint32_t koff = ks * 32;
            uint32_t afr[4][4], bfr[4][2];
#pragma unroll
            for (int mi = 0; mi < 4; mi++)
                ldsm_x4(afr[mi], abase + mi * 16 * (GSA * 2) + koff);
#pragma unroll
            for (int ni = 0; ni < 4; ni++)
                ldsm_x2(bfr[ni], bbase + ni * 8 * (GSA * 2) + koff);
#pragma unroll
            for (int mi = 0; mi < 4; mi++)
#pragma unroll
                for (int ni = 0; ni < 4; ni++)
                    mma_bf16(acc[mi][ni], afr[mi], bfr[ni]);
        }
        __syncthreads();
        if (t + 2 < 12) issue(t + 2, s);
    }

    // epilogue: tf32-rounded fp32 (consumed by tf32 mma in attn)
#pragma unroll
    for (int mi = 0; mi < 4; mi++) {
#pragma unroll
        for (int ni = 0; ni < 4; ni++) {
            int row = bm + wm + mi * 16 + qr;
            int col = bn + wn + ni * 8 + qc * 2;
            *(float2*)(&g_hp[(size_t)row * D + col]) =
                make_float2(tf32r(acc[mi][ni][0]), tf32r(acc[mi][ni][1]));
            *(float2*)(&g_hp[(size_t)(row + 8) * D + col]) =
                make_float2(tf32r(acc[mi][ni][2]), tf32r(acc[mi][ni][3]));
        }
    }
}

// ---------------------------------------------------------------------------
// Attention: per graph (1 CTA, 256 thr). Reads g_hp (tf32-valued fp32),
// writes g_ab (bf16) + g_h0 (fp32 row 0). Step 3 via tf32 mma.
// ---------------------------------------------------------------------------
__global__ __launch_bounds__(256) void attn_kernel(const float* __restrict__ batch,
                                                   const float* __restrict__ a_src,
                                                   const float* __restrict__ a_dst,
                                                   const float* __restrict__ bias) {
    __shared__ float s_attn[64][68];
    __shared__ float s_hs[64][72];
    __shared__ float s_src[64];
    __shared__ float s_dst[64];

    const int b = blockIdx.x;
    const int tid = threadIdx.x;
    const int warp = tid >> 5;
    const int lane = tid & 31;
    const int qr = lane >> 2;
    const int qc = lane & 3;
    const float* HP = g_hp + (size_t)b * NN * D;

    // ---- 1. src/dst row dots (tanh.approx) ----
    for (int i = warp; i < NN; i += 8) {
        float s = 0.f, dd = 0.f;
        const float* hrow = HP + (size_t)i * D;
#pragma unroll
        for (int o4 = lane * 4; o4 < D; o4 += 128) {
            float4 h  = *(const float4*)(hrow + o4);
            float4 as = *(const float4*)(a_src + o4);
            float4 ad = *(const float4*)(a_dst + o4);
            float t0 = tanhap(h.x), t1 = tanhap(h.y), t2 = tanhap(h.z), t3 = tanhap(h.w);
            s  = fmaf(t0, as.x, fmaf(t1, as.y, fmaf(t2, as.z, fmaf(t3, as.w, s))));
            dd = fmaf(t0, ad.x, fmaf(t1, ad.y, fmaf(t2, ad.z, fmaf(t3, ad.w, dd))));
        }
#pragma unroll
        for (int off = 16; off; off >>= 1) {
            s  += __shfl_xor_sync(0xffffffffu, s, off);
            dd += __shfl_xor_sync(0xffffffffu, dd, off);
        }
        if (lane == 0) { s_src[i] = s; s_dst[i] = dd; }
    }
    __syncthreads();

    // ---- 2. scores + softmax (tf32-rounded attn weights) ----
    for (int i = warp; i < NN; i += 8) {
        const float* arow = batch + ((size_t)b * NN + i) * ROWSTRIDE + D;
        float e0, e1;
        {
            int j = lane;
            float v = s_src[i] + s_dst[j];
            v = (v >= 0.f) ? v : NEG_SLOPE * v;
            bool allowed = (arow[j] != 0.f) || (i == j);
            e0 = allowed ? v : -INFINITY;
        }
        {
            int j = lane + 32;
            float v = s_src[i] + s_dst[j];
            v = (v >= 0.f) ? v : NEG_SLOPE * v;
            bool allowed = (arow[j] != 0.f) || (i == j);
            e1 = allowed ? v : -INFINITY;
        }
        float mx = fmaxf(e0, e1);
#pragma unroll
        for (int off = 16; off; off >>= 1)
            mx = fmaxf(mx, __shfl_xor_sync(0xffffffffu, mx, off));
        float x0 = (e0 == -INFINITY) ? 0.f : __expf(e0 - mx);
        float x1 = (e1 == -INFINITY) ? 0.f : __expf(e1 - mx);
        float sum = x0 + x1;
#pragma unroll
        for (int off = 16; off; off >>= 1)
            sum += __shfl_xor_sync(0xffffffffu, sum, off);
        float inv = 1.f / sum;
        s_attn[i][lane]      = tf32r(x0 * inv);
        s_attn[i][lane + 32] = tf32r(x1 * inv);
    }
    __syncthreads();

    // ---- 3. out = attn @ hp + bias via tf32 mma ----
    // warp tile: m 32 ((warp&1)*32) x n 16 ((warp>>1)*16); frags 2m x 2n x 8k
    const int wm_a = (warp & 1) * 32;
    const int wn_a = (warp >> 1) * 16;
    __nv_bfloat16* AOUT = g_ab + (size_t)b * NN * D;

    for (int dc = 0; dc < D; dc += 64) {
        for (int t = tid; t < 64 * 16; t += 256) {
            int r = t >> 4;
            int c4 = (t & 15) << 2;
            *(float4*)(&s_hs[r][c4]) = *(const float4*)(HP + (size_t)r * D + dc + c4);
        }
        __syncthreads();

        float acc[2][2][4];
#pragma unroll
        for (int mi = 0; mi < 2; mi++)
#pragma unroll
            for (int ni = 0; ni < 2; ni++)
#pragma unroll
                for (int u = 0; u < 4; u++) acc[mi][ni][u] = 0.f;

#pragma unroll
        for (int kk = 0; kk < 64; kk += 8) {
            float afr[2][4], bfr[2][2];
#pragma unroll
            for (int mi = 0; mi < 2; mi++) {
                int r = wm_a + mi * 16 + qr;
                afr[mi][0] = s_attn[r][kk + qc];
                afr[mi][1] = s_attn[r + 8][kk + qc];
                afr[mi][2] = s_attn[r][kk + qc + 4];
                afr[mi][3] = s_attn[r + 8][kk + qc + 4];
            }
#pragma unroll
            for (int ni = 0; ni < 2; ni++) {
                int c = wn_a + ni * 8 + qr;
                bfr[ni][0] = s_hs[kk + qc][c];
                bfr[ni][1] = s_hs[kk + qc + 4][c];
            }
#pragma unroll
            for (int mi = 0; mi < 2; mi++)
#pragma unroll
                for (int ni = 0; ni < 2; ni++)
                    mma_tf32(acc[mi][ni], afr[mi], bfr[ni]);
        }

        // epilogue: +bias, bf16 to g_ab; fp32 row 0 to g_h0
#pragma unroll
        for (int mi = 0; mi < 2; mi++) {
#pragma unroll
            for (int ni = 0; ni < 2; ni++) {
                int row = wm_a + mi * 16 + qr;
                int col = dc + wn_a + ni * 8 + qc * 2;
                float b0 = bias[col], b1 = bias[col + 1];
                float v0 = acc[mi][ni][0] + b0, v1 = acc[mi][ni][1] + b1;
                float v2 = acc[mi][ni][2] + b0, v3 = acc[mi][ni][3] + b1;
                __nv_bfloat162 p0 = __floats2bfloat162_rn(v0, v1);
                __nv_bfloat162 p1 = __floats2bfloat162_rn(v2, v3);
                *(uint32_t*)(AOUT + (size_t)row * D + col) = *(uint32_t*)&p0;
                *(uint32_t*)(AOUT + (size_t)(row + 8) * D + col) = *(uint32_t*)&p1;
                if (wm_a == 0 && mi == 0 && qr == 0)
                    *(float2*)(g_h0 + (size_t)b * D + col) = make_float2(v0, v1);
            }
        }
        __syncthreads();
    }
}

// ---------------------------------------------------------------------------
// final1: vec = [center(batch row0 feats), l2norm(g_h0[b])] into g_hp (512x1536)
// ---------------------------------------------------------------------------
__global__ __launch_bounds__(256) void final1_kernel(const float* __restrict__ batch) {
    const int b = blockIdx.x;
    const int tid = threadIdx.x;
    const int warp = tid >> 5, lane = tid & 31;
    __shared__ float red[8];

    const float* h0 = g_h0 + (size_t)b * D;
    float ss = 0.f;
    for (int o = tid; o < D; o += 256) { float v = h0[o]; ss = fmaf(v, v, ss); }
#pragma unroll
    for (int off = 16; off; off >>= 1) ss += __shfl_xor_sync(0xffffffffu, ss, off);
    if (lane == 0) red[warp] = ss;
    __syncthreads();
    float tot = red[0];
#pragma unroll
    for (int w = 1; w < 8; w++) tot += red[w];
    float inv = 1.f / fmaxf(sqrtf(tot), 1e-12f);

    float* vec = g_hp + (size_t)b * 1536;
    const float* crow = batch + (size_t)b * NN * ROWSTRIDE;
    for (int o = tid; o < D; o += 256) {
        vec[o]     = crow[o];
        vec[D + o] = h0[o] * inv;
    }
}

// ---------------------------------------------------------------------------
// final2: 4 graphs per CTA, out[b] = l2norm(vec[b] @ mlp_w.T + mlp_b)  (fp32)
// ---------------------------------------------------------------------------
__global__ __launch_bounds__(256) void final2_kernel(const float* __restrict__ mlp_w,
                                                     const float* __restrict__ mlp_b,
                                                     float* __restrict__ out) {
    __shared__ float sv[4][1536];
    __shared__ float sout[4][768];
    const int b0 = blockIdx.x * 4;
    const int tid = threadIdx.x;
    const int warp = tid >> 5, lane = tid & 31;

    for (int t = tid; t < 4 * 384; t += 256) {
        int g = t / 384;
        int k4 = (t % 384) << 2;
        *(float4*)(&sv[g][k4]) = *(const float4*)(g_hp + (size_t)(b0 + g) * 1536 + k4);
    }
    __syncthreads();

    for (int o = warp; o < 768; o += 8) {
        const float* wr = mlp_w + (size_t)o * 1536;
        float a0 = 0.f, a1 = 0.f, a2 = 0.f, a3 = 0.f;
        for (int k4 = lane * 4; k4 < 1536; k4 += 128) {
            float4 wv = *(const float4*)(wr + k4);
            float4 x;
            x = *(const float4*)(&sv[0][k4]); a0 += wv.x*x.x + wv.y*x.y + wv.z*x.z + wv.w*x.w;
            x = *(const float4*)(&sv[1][k4]); a1 += wv.x*x.x + wv.y*x.y + wv.z*x.z + wv.w*x.w;
            x = *(const float4*)(&sv[2][k4]); a2 += wv.x*x.x + wv.y*x.y + wv.z*x.z + wv.w*x.w;
            x = *(const float4*)(&sv[3][k4]); a3 += wv.x*x.x + wv.y*x.y + wv.z*x.z + wv.w*x.w;
        }
#pragma unroll
        for (int off = 16; off; off >>= 1) {
            a0 += __shfl_xor_sync(0xffffffffu, a0, off);
            a1 += __shfl_xor_sync(0xffffffffu, a1, off);
            a2 += __shfl_xor_sync(0xffffffffu, a2, off);
            a3 += __shfl_xor_sync(0xffffffffu, a3, off);
        }
        if (lane == 0) {
            float bo = mlp_b[o];
            sout[0][o] = a0 + bo;
            sout[1][o] = a1 + bo;
            sout[2][o] = a2 + bo;
            sout[3][o] = a3 + bo;
        }
    }
    __syncthreads();

    if (warp < 4) {
        float ss = 0.f;
        for (int o = lane; o < 768; o += 32) { float v = sout[warp][o]; ss = fmaf(v, v, ss); }
#pragma unroll
        for (int off = 16; off; off >>= 1) ss += __shfl_xor_sync(0xffffffffu, ss, off);
        float inv = 1.f / fmaxf(sqrtf(ss), 1e-12f);
        for (int o = lane; o < 768; o += 32)
            out[(size_t)(b0 + warp) * 768 + o] = sout[warp][o] * inv;
    }
}

// ---------------------------------------------------------------------------
extern "C" void kernel_launch(void* const* d_in, const int* in_sizes, int n_in,
                              void* d_out, int out_size) {
    const float* batch = (const float*)d_in[0];
    const float* w     = (const float*)d_in[1];
    const float* a_src = (const float*)d_in[2];
    const float* a_dst = (const float*)d_in[3];
    const float* gbias = (const float*)d_in[4];
    const float* mlp_w = (const float*)d_in[5];
    const float* mlp_b = (const float*)d_in[6];
    float* out = (float*)d_out;

    cudaFuncSetAttribute(gemm_bf16_kernel,
                         cudaFuncAttributeMaxDynamicSharedMemorySize, GSMEM);

    wconv_kernel<<<dim3(24, 24), 256>>>(w);
    aconv_kernel<<<512, 256>>>(batch);

    dim3 gg(6, 256);
    gemm_bf16_kernel<<<gg, 256, GSMEM>>>();
    attn_kernel<<<512, 256>>>(batch, a_src, a_dst, gbias);
    gemm_bf16_kernel<<<gg, 256, GSMEM>>>();
    attn_kernel<<<512, 256>>>(batch, a_src, a_dst, gbias);

    final1_kernel<<<512, 256>>>(batch);
    final2_kernel<<<128, 256>>>(mlp_w, mlp_b, out);
}

// round 8
// speedup vs baseline: 5.0377x; 1.2520x over previous
#include <cuda_runtime.h>
#include <cuda_bf16.h>
#include <math.h>
#include <stdint.h>

#define D 768
#define NN 64
#define BS 512
#define ROWSTRIDE 832   // D + NN
#define NEG_SLOPE 0.2f

// Scratch (allocation-free rule: __device__ globals).
__device__ float g_hp[BS * NN * D];            // fp32 GEMM out / concat buffer (512x1536)
__device__ __nv_bfloat16 g_ab[BS * NN * D];    // bf16 GEMM input A
__device__ float g_h0[BS * D];                 // attn row-0 output fp32
__device__ float g_ou[BS * D];                 // head output, unnormalized
__device__ __nv_bfloat16 g_wt[D * D];          // W^T bf16 [n][k]

__device__ __forceinline__ uint32_t smem_u32(const void* p) {
    uint32_t a;
    asm("{ .reg .u64 t; cvta.to.shared.u64 t, %1; cvt.u32.u64 %0, t; }" : "=r"(a) : "l"(p));
    return a;
}
__device__ __forceinline__ void ldsm_x4(uint32_t* r, uint32_t addr) {
    asm volatile("ldmatrix.sync.aligned.m8n8.x4.shared.b16 {%0,%1,%2,%3}, [%4];"
                 : "=r"(r[0]), "=r"(r[1]), "=r"(r[2]), "=r"(r[3]) : "r"(addr));
}
__device__ __forceinline__ void ldsm_x2(uint32_t* r, uint32_t addr) {
    asm volatile("ldmatrix.sync.aligned.m8n8.x2.shared.b16 {%0,%1}, [%2];"
                 : "=r"(r[0]), "=r"(r[1]) : "r"(addr));
}
__device__ __forceinline__ void mma_bf16(float* c, const uint32_t* a, const uint32_t* b) {
    asm volatile(
        "mma.sync.aligned.m16n8k16.row.col.f32.bf16.bf16.f32 "
        "{%0,%1,%2,%3}, {%4,%5,%6,%7}, {%8,%9}, {%0,%1,%2,%3};"
        : "+f"(c[0]), "+f"(c[1]), "+f"(c[2]), "+f"(c[3])
        : "r"(a[0]), "r"(a[1]), "r"(a[2]), "r"(a[3]), "r"(b[0]), "r"(b[1]));
}
__device__ __forceinline__ void mma_tf32(float* c, const float* a, const float* b) {
    asm volatile(
        "mma.sync.aligned.m16n8k8.row.col.f32.tf32.tf32.f32 "
        "{%0,%1,%2,%3}, {%4,%5,%6,%7}, {%8,%9}, {%0,%1,%2,%3};"
        : "+f"(c[0]), "+f"(c[1]), "+f"(c[2]), "+f"(c[3])
        : "r"(__float_as_uint(a[0])), "r"(__float_as_uint(a[1])),
          "r"(__float_as_uint(a[2])), "r"(__float_as_uint(a[3])),
          "r"(__float_as_uint(b[0])), "r"(__float_as_uint(b[1])));
}
__device__ __forceinline__ void cp_async16(uint32_t saddr, const void* g) {
    asm volatile("cp.async.cg.shared.global [%0], [%1], 16;" :: "r"(saddr), "l"(g) : "memory");
}
__device__ __forceinline__ float tanhap(float x) {
    float y; asm("tanh.approx.f32 %0, %1;" : "=f"(y) : "f"(x)); return y;
}
__device__ __forceinline__ float tf32r(float x) {
    uint32_t u;
    asm("cvt.rna.tf32.f32 %0, %1;" : "=r"(u) : "f"(x));
    return __uint_as_float(u);
}

// ---------------------------------------------------------------------------
// W convert: g_wt[n][k] = bf16(W[k][n])
// ---------------------------------------------------------------------------
__global__ __launch_bounds__(256) void wconv_kernel(const float* __restrict__ W) {
    __shared__ float tile[32][33];
    const int n0 = blockIdx.x * 32, k0 = blockIdx.y * 32;
    const int tx = threadIdx.x & 31, ty = threadIdx.x >> 5;
#pragma unroll
    for (int i = ty; i < 32; i += 8)
        tile[i][tx] = W[(size_t)(k0 + i) * D + n0 + tx];
    __syncthreads();
#pragma unroll
    for (int i = ty; i < 32; i += 8)
        g_wt[(size_t)(n0 + i) * D + k0 + tx] = __float2bfloat16(tile[tx][i]);
}

// ---------------------------------------------------------------------------
// A convert (layer 0): g_ab = bf16(batch features), strided 832 -> dense 768
// ---------------------------------------------------------------------------
__global__ __launch_bounds__(256) void aconv_kernel(const float* __restrict__ batch) {
    const int b = blockIdx.x;
    const float* src = batch + (size_t)b * NN * ROWSTRIDE;
    __nv_bfloat16* dst = g_ab + (size_t)b * NN * D;
    for (int idx = threadIdx.x; idx < NN * (D / 4); idx += 256) {
        int row = idx / (D / 4);
        int q = (idx % (D / 4)) * 4;
        float4 v = *(const float4*)(src + (size_t)row * ROWSTRIDE + q);
        __nv_bfloat162 lo = __floats2bfloat162_rn(v.x, v.y);
        __nv_bfloat162 hi = __floats2bfloat162_rn(v.z, v.w);
        uint2 pk;
        pk.x = *(uint32_t*)&lo;
        pk.y = *(uint32_t*)&hi;
        *(uint2*)(dst + (size_t)row * D + q) = pk;
    }
}

// ---------------------------------------------------------------------------
// BF16 tensor-core GEMM: g_hp = g_ab @ g_wt^T (tf32-rounded outputs)
// CTA tile 128x128, BK=64, 2-stage cp.async, 8 warps (2m x 4n). (unchanged)
// ---------------------------------------------------------------------------
#define GSA 72
#define GSTAGE 36864
#define GSMEM  (2 * GSTAGE)

__global__ __launch_bounds__(256) void gemm_bf16_kernel() {
    extern __shared__ char smem[];
    const uint32_t sb = smem_u32(smem);

    const int tid  = threadIdx.x;
    const int wid  = tid >> 5;
    const int lane = tid & 31;
    const int bm   = blockIdx.y * 128;
    const int bn   = blockIdx.x * 128;
    const int wm   = (wid >> 2) * 64;
    const int wn   = (wid & 3) * 32;
    const int qr   = lane >> 2;
    const int qc   = lane & 3;

    int lrow[4], lc8[4];
#pragma unroll
    for (int i = 0; i < 4; i++) {
        int idx = i * 256 + tid;
        lrow[i] = idx >> 3;
        lc8[i]  = (idx & 7) * 8;
    }

    const uint32_t a_off = (uint32_t)(((wm + (lane & 15)) * GSA + (lane >> 4) * 8) * 2);
    const uint32_t b_off = (uint32_t)(((wn + (lane & 7)) * GSA + ((lane >> 3) & 1) * 8) * 2);

    float acc[4][4][4];
#pragma unroll
    for (int mi = 0; mi < 4; mi++)
#pragma unroll
        for (int ni = 0; ni < 4; ni++)
#pragma unroll
            for (int u = 0; u < 4; u++) acc[mi][ni][u] = 0.f;

    auto issue = [&](int t, int s) {
        const int k0 = t * 64;
        const uint32_t abase = sb + (uint32_t)s * GSTAGE;
        const uint32_t bbase = abase + 18432;
#pragma unroll
        for (int i = 0; i < 4; i++)
            cp_async16(abase + (uint32_t)((lrow[i] * GSA + lc8[i]) * 2),
                       g_ab + (size_t)(bm + lrow[i]) * D + k0 + lc8[i]);
#pragma unroll
        for (int i = 0; i < 4; i++)
            cp_async16(bbase + (uint32_t)((lrow[i] * GSA + lc8[i]) * 2),
                       g_wt + (size_t)(bn + lrow[i]) * D + k0 + lc8[i]);
        asm volatile("cp.async.commit_group;" ::: "memory");
    };

    issue(0, 0);
    issue(1, 1);

#pragma unroll 1
    for (int t = 0; t < 12; t++) {
        const int s = t & 1;
        if (t < 10) asm volatile("cp.async.wait_group 1;" ::: "memory");
        else        asm volatile("cp.async.wait_group 0;" ::: "memory");
        __syncthreads();

        const uint32_t abase = sb + (uint32_t)s * GSTAGE + a_off;
        const uint32_t bbase = sb + (uint32_t)s * GSTAGE + 18432 + b_off;
#pragma unroll
        for (int ks = 0; ks < 4; ks++) {
            const uint32_t koff = ks * 32;
            uint32_t afr[4][4], bfr[4][2];
#pragma unroll
            for (int mi = 0; mi < 4; mi++)
                ldsm_x4(afr[mi], abase + mi * 16 * (GSA * 2) + koff);
#pragma unroll
            for (int ni = 0; ni < 4; ni++)
                ldsm_x2(bfr[ni], bbase + ni * 8 * (GSA * 2) + koff);
#pragma unroll
            for (int mi = 0; mi < 4; mi++)
#pragma unroll
                for (int ni = 0; ni < 4; ni++)
                    mma_bf16(acc[mi][ni], afr[mi], bfr[ni]);
        }
        __syncthreads();
        if (t + 2 < 12) issue(t + 2, s);
    }

#pragma unroll
    for (int mi = 0; mi < 4; mi++) {
#pragma unroll
        for (int ni = 0; ni < 4; ni++) {
            int row = bm + wm + mi * 16 + qr;
            int col = bn + wn + ni * 8 + qc * 2;
            *(float2*)(&g_hp[(size_t)row * D + col]) =
                make_float2(tf32r(acc[mi][ni][0]), tf32r(acc[mi][ni][1]));
            *(float2*)(&g_hp[(size_t)(row + 8) * D + col]) =
                make_float2(tf32r(acc[mi][ni][2]), tf32r(acc[mi][ni][3]));
        }
    }
}

// ---------------------------------------------------------------------------
// Attention: per graph, 512 threads (16 warps), full HP resident in smem.
// smem: s_hs[64][776] fp32 (198656B) + s_attn[64][68] (17408B) + src/dst.
// 2 syncthreads total. Step 3: tf32 mma from smem, warp tile 32x48 x 2 halves.
// ---------------------------------------------------------------------------
#define A_HS_STRIDE 776
#define A_HS_FLOATS (64 * A_HS_STRIDE)          // 49664
#define A_ATT_OFF   A_HS_FLOATS                 // s_attn base (floats)
#define A_SRC_OFF   (A_ATT_OFF + 64 * 68)       // 54016
#define A_DST_OFF   (A_SRC_OFF + 64)
#define ASMEM       ((A_DST_OFF + 64) * 4)      // 216,576 bytes

__global__ __launch_bounds__(512) void attn_kernel(const float* __restrict__ batch,
                                                   const float* __restrict__ a_src,
                                                   const float* __restrict__ a_dst,
                                                   const float* __restrict__ bias) {
    extern __shared__ float sm[];
    float* s_hs   = sm;
    float* s_attn = sm + A_ATT_OFF;   // [64][68]
    float* s_src  = sm + A_SRC_OFF;
    float* s_dst  = sm + A_DST_OFF;

    const int b = blockIdx.x;
    const int tid = threadIdx.x;
    const int warp = tid >> 5;
    const int lane = tid & 31;
    const int qr = lane >> 2;
    const int qc = lane & 3;
    const float* HP = g_hp + (size_t)b * NN * D;

    // ---- 1. load HP -> smem + tanh dots (4 rows per warp) ----
    for (int i = warp; i < NN; i += 16) {
        float s = 0.f, dd = 0.f;
        const float* hrow = HP + (size_t)i * D;
        float* hsrow = s_hs + i * A_HS_STRIDE;
#pragma unroll
        for (int o4 = lane * 4; o4 < D; o4 += 128) {
            float4 h  = *(const float4*)(hrow + o4);
            *(float4*)(hsrow + o4) = h;
            float4 as = *(const float4*)(a_src + o4);
            float4 ad = *(const float4*)(a_dst + o4);
            float t0 = tanhap(h.x), t1 = tanhap(h.y), t2 = tanhap(h.z), t3 = tanhap(h.w);
            s  = fmaf(t0, as.x, fmaf(t1, as.y, fmaf(t2, as.z, fmaf(t3, as.w, s))));
            dd = fmaf(t0, ad.x, fmaf(t1, ad.y, fmaf(t2, ad.z, fmaf(t3, ad.w, dd))));
        }
#pragma unroll
        for (int off = 16; off; off >>= 1) {
            s  += __shfl_xor_sync(0xffffffffu, s, off);
            dd += __shfl_xor_sync(0xffffffffu, dd, off);
        }
        if (lane == 0) { s_src[i] = s; s_dst[i] = dd; }
    }
    __syncthreads();

    // ---- 2. scores + softmax (tf32-rounded attn weights) ----
    for (int i = warp; i < NN; i += 16) {
        const float* arow = batch + ((size_t)b * NN + i) * ROWSTRIDE + D;
        float e0, e1;
        {
            int j = lane;
            float v = s_src[i] + s_dst[j];
            v = (v >= 0.f) ? v : NEG_SLOPE * v;
            bool allowed = (arow[j] != 0.f) || (i == j);
            e0 = allowed ? v : -INFINITY;
        }
        {
            int j = lane + 32;
            float v = s_src[i] + s_dst[j];
            v = (v >= 0.f) ? v : NEG_SLOPE * v;
            bool allowed = (arow[j] != 0.f) || (i == j);
            e1 = allowed ? v : -INFINITY;
        }
        float mx = fmaxf(e0, e1);
#pragma unroll
        for (int off = 16; off; off >>= 1)
            mx = fmaxf(mx, __shfl_xor_sync(0xffffffffu, mx, off));
        float x0 = (e0 == -INFINITY) ? 0.f : __expf(e0 - mx);
        float x1 = (e1 == -INFINITY) ? 0.f : __expf(e1 - mx);
        float sum = x0 + x1;
#pragma unroll
        for (int off = 16; off; off >>= 1)
            sum += __shfl_xor_sync(0xffffffffu, sum, off);
        float inv = 1.f / sum;
        s_attn[i * 68 + lane]      = tf32r(x0 * inv);
        s_attn[i * 68 + lane + 32] = tf32r(x1 * inv);
    }
    __syncthreads();

    // ---- 3. out = attn @ hp + bias via tf32 mma from smem ----
    // 16 warps: 2(m) x 8(n); warp tile 32 x 48, two n-halves (+0, +384)
    const int wm_a = (warp & 1) * 32;
    const int wn_b = (warp >> 1) * 48;
    __nv_bfloat16* AOUT = g_ab + (size_t)b * NN * D;

#pragma unroll
    for (int half = 0; half < 2; half++) {
        const int n0 = wn_b + half * 384;
        float acc[2][6][4];
#pragma unroll
        for (int mi = 0; mi < 2; mi++)
#pragma unroll
            for (int ni = 0; ni < 6; ni++)
#pragma unroll
                for (int u = 0; u < 4; u++) acc[mi][ni][u] = 0.f;

#pragma unroll
        for (int kk = 0; kk < 64; kk += 8) {
            float afr[2][4], bfr[6][2];
#pragma unroll
            for (int mi = 0; mi < 2; mi++) {
                int r = wm_a + mi * 16 + qr;
                afr[mi][0] = s_attn[r * 68 + kk + qc];
                afr[mi][1] = s_attn[(r + 8) * 68 + kk + qc];
                afr[mi][2] = s_attn[r * 68 + kk + qc + 4];
                afr[mi][3] = s_attn[(r + 8) * 68 + kk + qc + 4];
            }
#pragma unroll
            for (int ni = 0; ni < 6; ni++) {
                int c = n0 + ni * 8 + qr;
                bfr[ni][0] = s_hs[(kk + qc) * A_HS_STRIDE + c];
                bfr[ni][1] = s_hs[(kk + qc + 4) * A_HS_STRIDE + c];
            }
#pragma unroll
            for (int mi = 0; mi < 2; mi++)
#pragma unroll
                for (int ni = 0; ni < 6; ni++)
                    mma_tf32(acc[mi][ni], afr[mi], bfr[ni]);
        }

        // epilogue: +bias, bf16 to g_ab; fp32 row 0 to g_h0
#pragma unroll
        for (int mi = 0; mi < 2; mi++) {
#pragma unroll
            for (int ni = 0; ni < 6; ni++) {
                int row = wm_a + mi * 16 + qr;
                int col = n0 + ni * 8 + qc * 2;
                float b0 = bias[col], b1 = bias[col + 1];
                float v0 = acc[mi][ni][0] + b0, v1 = acc[mi][ni][1] + b1;
                float v2 = acc[mi][ni][2] + b0, v3 = acc[mi][ni][3] + b1;
                __nv_bfloat162 p0 = __floats2bfloat162_rn(v0, v1);
                __nv_bfloat162 p1 = __floats2bfloat162_rn(v2, v3);
                *(uint32_t*)(AOUT + (size_t)row * D + col) = *(uint32_t*)&p0;
                *(uint32_t*)(AOUT + (size_t)(row + 8) * D + col) = *(uint32_t*)&p1;
                if (wm_a == 0 && mi == 0 && qr == 0)
                    *(float2*)(g_h0 + (size_t)b * D + col) = make_float2(v0, v1);
            }
        }
    }
}

// ---------------------------------------------------------------------------
// final1: vec = [center(batch row0 feats), l2norm(g_h0[b])] into g_hp (512x1536)
// ---------------------------------------------------------------------------
__global__ __launch_bounds__(256) void final1_kernel(const float* __restrict__ batch) {
    const int b = blockIdx.x;
    const int tid = threadIdx.x;
    const int warp = tid >> 5, lane = tid & 31;
    __shared__ float red[8];

    const float* h0 = g_h0 + (size_t)b * D;
    float ss = 0.f;
    for (int o = tid; o < D; o += 256) { float v = h0[o]; ss = fmaf(v, v, ss); }
#pragma unroll
    for (int off = 16; off; off >>= 1) ss += __shfl_xor_sync(0xffffffffu, ss, off);
    if (lane == 0) red[warp] = ss;
    __syncthreads();
    float tot = red[0];
#pragma unroll
    for (int w = 1; w < 8; w++) tot += red[w];
    float inv = 1.f / fmaxf(sqrtf(tot), 1e-12f);

    float* vec = g_hp + (size_t)b * 1536;
    const float* crow = batch + (size_t)b * NN * ROWSTRIDE;
    for (int o = tid; o < D; o += 256) {
        vec[o]     = crow[o];
        vec[D + o] = h0[o] * inv;
    }
}

// ---------------------------------------------------------------------------
// final2: grid (4 n-blocks x 32 graph-blocks), 16 graphs/CTA in smem.
// g_ou[b][o] = vec[b] . mlp_w[o] + mlp_b[o]   (fp32, unnormalized)
// ---------------------------------------------------------------------------
__global__ __launch_bounds__(256) void final2_kernel(const float* __restrict__ mlp_w,
                                                     const float* __restrict__ mlp_b) {
    __shared__ float sv[16][1536];   // 98 KB
    const int n0 = blockIdx.x * 192;
    const int b0 = blockIdx.y * 16;
    const int tid = threadIdx.x;
    const int warp = tid >> 5, lane = tid & 31;

    for (int t = tid; t < 16 * 384; t += 256) {
        int g = t / 384;
        int k4 = (t % 384) << 2;
        *(float4*)(&sv[g][k4]) = *(const float4*)(g_hp + (size_t)(b0 + g) * 1536 + k4);
    }
    __syncthreads();

    for (int o = n0 + warp; o < n0 + 192; o += 8) {
        const float* wr = mlp_w + (size_t)o * 1536;
        float a[16];
#pragma unroll
        for (int g = 0; g < 16; g++) a[g] = 0.f;
        for (int k4 = lane * 4; k4 < 1536; k4 += 128) {
            float4 wv = *(const float4*)(wr + k4);
#pragma unroll
            for (int g = 0; g < 16; g++) {
                float4 x = *(const float4*)(&sv[g][k4]);
                a[g] += wv.x * x.x + wv.y * x.y + wv.z * x.z + wv.w * x.w;
            }
        }
#pragma unroll
        for (int g = 0; g < 16; g++) {
#pragma unroll
            for (int off = 16; off; off >>= 1)
                a[g] += __shfl_xor_sync(0xffffffffu, a[g], off);
        }
        float bo = mlp_b[o];
#pragma unroll
        for (int g = 0; g < 16; g++)
            if (lane == g) g_ou[(size_t)(b0 + g) * D + o] = a[g] + bo;
    }
}

// ---------------------------------------------------------------------------
// final3: out[b] = l2norm(g_ou[b])
// ---------------------------------------------------------------------------
__global__ __launch_bounds__(256) void final3_kernel(float* __restrict__ out) {
    const int b = blockIdx.x;
    const int tid = threadIdx.x;
    const int warp = tid >> 5, lane = tid & 31;
    __shared__ float red[8];

    const float* r = g_ou + (size_t)b * D;
    float ss = 0.f;
    for (int o = tid; o < D; o += 256) { float v = r[o]; ss = fmaf(v, v, ss); }
#pragma unroll
    for (int off = 16; off; off >>= 1) ss += __shfl_xor_sync(0xffffffffu, ss, off);
    if (lane == 0) red[warp] = ss;
    __syncthreads();
    float tot = red[0];
#pragma unroll
    for (int w = 1; w < 8; w++) tot += red[w];
    float inv = 1.f / fmaxf(sqrtf(tot), 1e-12f);
    for (int o = tid; o < D; o += 256)
        out[(size_t)b * D + o] = r[o] * inv;
}

// ---------------------------------------------------------------------------
extern "C" void kernel_launch(void* const* d_in, const int* in_sizes, int n_in,
                              void* d_out, int out_size) {
    const float* batch = (const float*)d_in[0];
    const float* w     = (const float*)d_in[1];
    const float* a_src = (const float*)d_in[2];
    const float* a_dst = (const float*)d_in[3];
    const float* gbias = (const float*)d_in[4];
    const float* mlp_w = (const float*)d_in[5];
    const float* mlp_b = (const float*)d_in[6];
    float* out = (float*)d_out;

    cudaFuncSetAttribute(gemm_bf16_kernel,
                         cudaFuncAttributeMaxDynamicSharedMemorySize, GSMEM);
    cudaFuncSetAttribute(attn_kernel,
                         cudaFuncAttributeMaxDynamicSharedMemorySize, ASMEM);

    wconv_kernel<<<dim3(24, 24), 256>>>(w);
    aconv_kernel<<<512, 256>>>(batch);

    dim3 gg(6, 256);
    gemm_bf16_kernel<<<gg, 256, GSMEM>>>();
    attn_kernel<<<512, 512, ASMEM>>>(batch, a_src, a_dst, gbias);
    gemm_bf16_kernel<<<gg, 256, GSMEM>>>();
    attn_kernel<<<512, 512, ASMEM>>>(batch, a_src, a_dst, gbias);

    final1_kernel<<<512, 256>>>(batch);
    final2_kernel<<<dim3(4, 32), 256>>>(mlp_w, mlp_b);
    final3_kernel<<<512, 256>>>(out);
}